// round 4
// baseline (speedup 1.0000x reference)
#include <cuda_runtime.h>
#include <cstdint>
#include <cstddef>

// Problem shapes (fixed for this benchmark)
#define NROWS 32768
#define D_IN  1024
#define HID   1024
#define INTD  2048

// ---------------- scratch (device globals: allocation-free rule) ------------
__device__ int   g_cnt0;
__device__ int   g_cnt1;
__device__ int   g_perm[NROWS];
__device__ float g_h1 [(size_t)NROWS * HID];   // hidden buffer (reused for both hiddens)
__device__ float g_enc[(size_t)NROWS * INTD];  // encoder output

// ---------------- routing: partition rows by language -----------------------
__global__ void init_counters_kernel() {
    g_cnt0 = 0;
    g_cnt1 = 0;
}

// lang==0 rows compact to the front [0,n0), lang==1 rows to the back [n0,N).
// Atomic order varies run-to-run but each row's computation is identical
// wherever it lands, and the final scatter restores original positions, so
// the OUTPUT is deterministic.
__global__ void build_perm_kernel(const int* __restrict__ lang, int n) {
    int i = blockIdx.x * blockDim.x + threadIdx.x;
    if (i < n) {
        if (lang[i] == 0) {
            int p = atomicAdd(&g_cnt0, 1);
            g_perm[p] = i;
        } else {
            int p = atomicAdd(&g_cnt1, 1);
            g_perm[n - 1 - p] = i;
        }
    }
}

// ---------------- tf32 tiled GEMM with mma.sync ------------------------------
#define BM 128
#define BN 128
#define BK 16

__device__ __forceinline__ uint32_t f2tf(float x) {
    uint32_t u;
    asm("cvt.rna.tf32.f32 %0, %1;" : "=r"(u) : "f"(x));
    return u;
}

// C[M,N] = act(A[M,K] @ B[K,N] + bias), with optional:
//   SPLIT:   rows [0,n0) use (B0,bias0), rows [n0,M) use (B1,bias1);
//            blockIdx.z selects the expert; boundary tiles are row-masked.
//   GATHER:  A row m is read from A[g_perm[m]] (layer 1 reads x permuted).
//   SCATTER: C row m is written to C[g_perm[m]] (layer 4 un-permutes).
template<bool RELU, bool GATHER, bool SCATTER, bool SPLIT>
__global__ void __launch_bounds__(256)
gemm_tf32_kernel(const float* __restrict__ A,
                 const float* __restrict__ B0, const float* __restrict__ B1,
                 const float* __restrict__ bias0, const float* __restrict__ bias1,
                 float* __restrict__ C, int M, int N, int K)
{
    __shared__ uint32_t As[BM][BK + 4];   // stride 20: conflict-free A-frag loads
    __shared__ uint32_t Bs[BK][BN + 8];   // stride 136: conflict-free B-frag loads

    const int n0 = SPLIT ? g_cnt0 : M;
    const int e  = SPLIT ? (int)blockIdx.z : 0;
    const int lo = (e == 0) ? 0  : n0;
    const int hi = (e == 0) ? n0 : M;
    const int row0 = blockIdx.y * BM;
    if (SPLIT && (row0 >= hi || row0 + BM <= lo)) return;
    const int col0 = blockIdx.x * BN;

    const float* __restrict__ B    = (e == 0) ? B0    : B1;
    const float* __restrict__ bias = (e == 0) ? bias0 : bias1;

    const int tid  = threadIdx.x;
    const int warp = tid >> 5;
    const int lane = tid & 31;
    const int warpM = warp >> 2;          // 0..1  (64 rows each)
    const int warpN = warp & 3;           // 0..3  (32 cols each)
    const int g  = lane >> 2;             // groupID 0..7
    const int tg = lane & 3;              // thread-in-group 0..3

    float acc[4][4][4];
    #pragma unroll
    for (int mt = 0; mt < 4; mt++)
        #pragma unroll
        for (int nt = 0; nt < 4; nt++)
            #pragma unroll
            for (int i = 0; i < 4; i++)
                acc[mt][nt][i] = 0.0f;

    // Precompute A-load source rows (2 float4 loads per thread per tile).
    int  aRow[2];
    bool aValid[2];
    #pragma unroll
    for (int s = 0; s < 2; s++) {
        int i = tid + s * 256;
        int r = i >> 2;
        int m = row0 + r;
        bool v = (!SPLIT) || (m >= lo && m < hi);
        aValid[s] = v;
        aRow[s]   = GATHER ? (v ? g_perm[m] : 0) : m;
    }

    for (int k0 = 0; k0 < K; k0 += BK) {
        // ---- load A tile (128x16), convert to tf32 ----
        #pragma unroll
        for (int s = 0; s < 2; s++) {
            int i = tid + s * 256;
            int r = i >> 2;
            int c = (i & 3) * 4;
            float4 v = make_float4(0.f, 0.f, 0.f, 0.f);
            if (aValid[s])
                v = *(const float4*)(A + (size_t)aRow[s] * K + k0 + c);
            As[r][c + 0] = f2tf(v.x);
            As[r][c + 1] = f2tf(v.y);
            As[r][c + 2] = f2tf(v.z);
            As[r][c + 3] = f2tf(v.w);
        }
        // ---- load B tile (16x128), convert to tf32 ----
        #pragma unroll
        for (int s = 0; s < 2; s++) {
            int i = tid + s * 256;
            int kk = i >> 5;
            int c  = (i & 31) * 4;
            float4 v = *(const float4*)(B + (size_t)(k0 + kk) * N + col0 + c);
            Bs[kk][c + 0] = f2tf(v.x);
            Bs[kk][c + 1] = f2tf(v.y);
            Bs[kk][c + 2] = f2tf(v.z);
            Bs[kk][c + 3] = f2tf(v.w);
        }
        __syncthreads();

        #pragma unroll
        for (int kk = 0; kk < BK; kk += 8) {
            uint32_t af[4][4];
            uint32_t bf[4][2];
            #pragma unroll
            for (int mt = 0; mt < 4; mt++) {
                int r = warpM * 64 + mt * 16;
                af[mt][0] = As[r + g    ][kk + tg    ];
                af[mt][1] = As[r + g + 8][kk + tg    ];
                af[mt][2] = As[r + g    ][kk + tg + 4];
                af[mt][3] = As[r + g + 8][kk + tg + 4];
            }
            #pragma unroll
            for (int nt = 0; nt < 4; nt++) {
                int c = warpN * 32 + nt * 8 + g;
                bf[nt][0] = Bs[kk + tg    ][c];
                bf[nt][1] = Bs[kk + tg + 4][c];
            }
            #pragma unroll
            for (int mt = 0; mt < 4; mt++)
                #pragma unroll
                for (int nt = 0; nt < 4; nt++) {
                    asm volatile(
                        "mma.sync.aligned.m16n8k8.row.col.f32.tf32.tf32.f32 "
                        "{%0,%1,%2,%3}, {%4,%5,%6,%7}, {%8,%9}, {%0,%1,%2,%3};"
                        : "+f"(acc[mt][nt][0]), "+f"(acc[mt][nt][1]),
                          "+f"(acc[mt][nt][2]), "+f"(acc[mt][nt][3])
                        : "r"(af[mt][0]), "r"(af[mt][1]),
                          "r"(af[mt][2]), "r"(af[mt][3]),
                          "r"(bf[nt][0]), "r"(bf[nt][1]));
                }
        }
        __syncthreads();
    }

    // ---- epilogue: bias (+ReLU), expert-row mask, optional scatter ----
    #pragma unroll
    for (int mt = 0; mt < 4; mt++) {
        #pragma unroll
        for (int nt = 0; nt < 4; nt++) {
            int c = col0 + warpN * 32 + nt * 8 + tg * 2;
            float bv0 = bias[c];
            float bv1 = bias[c + 1];
            #pragma unroll
            for (int half = 0; half < 2; half++) {
                int m = row0 + warpM * 64 + mt * 16 + g + half * 8;
                if (SPLIT && (m < lo || m >= hi)) continue;
                float v0 = acc[mt][nt][half * 2 + 0] + bv0;
                float v1 = acc[mt][nt][half * 2 + 1] + bv1;
                if (RELU) { v0 = fmaxf(v0, 0.f); v1 = fmaxf(v1, 0.f); }
                int mo = SCATTER ? g_perm[m] : m;
                *(float2*)(C + (size_t)mo * N + c) = make_float2(v0, v1);
            }
        }
    }
}

// ---------------- launch ------------------------------------------------------
extern "C" void kernel_launch(void* const* d_in, const int* in_sizes, int n_in,
                              void* d_out, int out_size)
{
    const float* x     = (const float*)d_in[0];
    const int*   lang  = (const int*)  d_in[1];
    const float* W_de1 = (const float*)d_in[2];
    const float* b_de1 = (const float*)d_in[3];
    const float* W_de2 = (const float*)d_in[4];
    const float* b_de2 = (const float*)d_in[5];
    const float* W_nl1 = (const float*)d_in[6];
    const float* b_nl1 = (const float*)d_in[7];
    const float* W_nl2 = (const float*)d_in[8];
    const float* b_nl2 = (const float*)d_in[9];
    const float* W_d1  = (const float*)d_in[10];
    const float* b_d1  = (const float*)d_in[11];
    const float* W_d2  = (const float*)d_in[12];
    const float* b_d2  = (const float*)d_in[13];
    float* out = (float*)d_out;

    const int M = in_sizes[1];  // 32768

    float* h1  = nullptr;
    float* enc = nullptr;
    cudaGetSymbolAddress((void**)&h1,  g_h1);
    cudaGetSymbolAddress((void**)&enc, g_enc);

    init_counters_kernel<<<1, 1>>>();
    build_perm_kernel<<<(M + 255) / 256, 256>>>(lang, M);

    // Layer 1: h1[m] = relu(x[perm[m]] @ W1_e + b1_e), expert-split rows
    {
        dim3 grid(HID / BN, M / BM, 2);
        gemm_tf32_kernel<true, true, false, true><<<grid, 256>>>(
            x, W_de1, W_nl1, b_de1, b_nl1, h1, M, HID, D_IN);
    }
    // Layer 2: enc[m] = h1[m] @ W2_e + b2_e, expert-split rows
    {
        dim3 grid(INTD / BN, M / BM, 2);
        gemm_tf32_kernel<false, false, false, true><<<grid, 256>>>(
            h1, W_de2, W_nl2, b_de2, b_nl2, enc, M, INTD, HID);
    }
    // Layer 3: h1[m] = relu(enc[m] @ W_d1 + b_d1), shared decoder
    {
        dim3 grid(HID / BN, M / BM, 1);
        gemm_tf32_kernel<true, false, false, false><<<grid, 256>>>(
            enc, W_d1, W_d1, b_d1, b_d1, h1, M, HID, INTD);
    }
    // Layer 4: out[perm[m]] = h1[m] @ W_d2 + b_d2, scatter rows back
    {
        dim3 grid(D_IN / BN, M / BM, 1);
        gemm_tf32_kernel<false, false, true, false><<<grid, 256>>>(
            h1, W_d2, W_d2, b_d2, b_d2, out, M, D_IN, HID);
    }
}

// round 6
// speedup vs baseline: 1.9416x; 1.9416x over previous
#include <cuda_runtime.h>
#include <cuda_fp16.h>
#include <cstdint>
#include <cstddef>

// Problem shapes (fixed)
#define NROWS 32768
#define D_IN  1024
#define HID   1024
#define INTD  2048

// GEMM tiling
#define BM 128
#define BN 128
#define BK 32               // halfs per chunk
#define STAGES 4
#define ROWB 80             // smem row stride bytes (32 halfs = 64B + 16B pad)
#define A_ST (BM * ROWB)    // 10240
#define B_ST (BN * ROWB)    // 10240
#define STAGE_BYTES (A_ST + B_ST)
#define SMEM_DYN (STAGES * STAGE_BYTES)   // 81920

// ---------------- scratch (device globals: allocation-free rule) ------------
__device__ int    g_cnt0, g_cnt1;
__device__ int    g_perm[NROWS];
__device__ __half g_xh [(size_t)NROWS * D_IN];
__device__ __half g_h1 [(size_t)NROWS * HID];
__device__ __half g_enc[(size_t)NROWS * INTD];
// Pre-transposed half weights: [n][k] K-major
__device__ __half g_Wt_e1[(size_t)2 * HID  * D_IN];
__device__ __half g_Wt_e2[(size_t)2 * INTD * HID ];
__device__ __half g_Wt_d1[(size_t)HID  * INTD];
__device__ __half g_Wt_d2[(size_t)D_IN * HID ];

// ---------------- helpers ----------------------------------------------------
__device__ __forceinline__ uint32_t smem_u32(const void* p) {
    uint32_t a;
    asm("{ .reg .u64 t; cvta.to.shared.u64 t, %1; cvt.u32.u64 %0, t; }" : "=r"(a) : "l"(p));
    return a;
}

#define CP_ASYNC16(dst, src, sz) \
    asm volatile("cp.async.cg.shared.global [%0], [%1], 16, %2;" \
                 :: "r"(dst), "l"(src), "r"(sz) : "memory")
#define CP_COMMIT() asm volatile("cp.async.commit_group;" ::: "memory")
#define CP_WAIT(n)  asm volatile("cp.async.wait_group %0;" :: "n"(n) : "memory")

#define LDSM_X4(r0, r1, r2, r3, addr) \
    asm volatile("ldmatrix.sync.aligned.m8n8.x4.shared.b16 {%0,%1,%2,%3}, [%4];" \
                 : "=r"(r0), "=r"(r1), "=r"(r2), "=r"(r3) : "r"(addr))

#define MMA16816(d, a, b) \
    asm volatile("mma.sync.aligned.m16n8k16.row.col.f32.f16.f16.f32 " \
                 "{%0,%1,%2,%3}, {%4,%5,%6,%7}, {%8,%9}, {%0,%1,%2,%3};" \
                 : "+f"((d)[0]), "+f"((d)[1]), "+f"((d)[2]), "+f"((d)[3]) \
                 : "r"((a)[0]), "r"((a)[1]), "r"((a)[2]), "r"((a)[3]), \
                   "r"((b)[0]), "r"((b)[1]))

// ---------------- routing ----------------------------------------------------
__global__ void init_counters_kernel() { g_cnt0 = 0; g_cnt1 = 0; }

__global__ void build_perm_kernel(const int* __restrict__ lang, int n) {
    int i = blockIdx.x * blockDim.x + threadIdx.x;
    if (i < n) {
        if (lang[i] == 0) g_perm[atomicAdd(&g_cnt0, 1)] = i;
        else              g_perm[n - 1 - atomicAdd(&g_cnt1, 1)] = i;
    }
}

// ---------------- prep: f32 -> f16 convert / transpose -----------------------
__global__ void f2h_kernel(const float* __restrict__ in, __half* __restrict__ out,
                           int n) {
    int i = (blockIdx.x * blockDim.x + threadIdx.x) * 8;
    if (i < n) {
        float4 a = *(const float4*)(in + i);
        float4 b = *(const float4*)(in + i + 4);
        __half h[8];
        h[0] = __float2half_rn(a.x); h[1] = __float2half_rn(a.y);
        h[2] = __float2half_rn(a.z); h[3] = __float2half_rn(a.w);
        h[4] = __float2half_rn(b.x); h[5] = __float2half_rn(b.y);
        h[6] = __float2half_rn(b.z); h[7] = __float2half_rn(b.w);
        *(uint4*)(out + i) = *(const uint4*)h;
    }
}

// in: [K, N] row-major f32 -> out: [N, K] row-major half
__global__ void transpose_h_kernel(const float* __restrict__ in,
                                   __half* __restrict__ out, int K, int N) {
    __shared__ float t[32][33];
    int n0 = blockIdx.x * 32, k0 = blockIdx.y * 32;
    #pragma unroll
    for (int j = threadIdx.y; j < 32; j += 8)
        t[j][threadIdx.x] = in[(size_t)(k0 + j) * N + n0 + threadIdx.x];
    __syncthreads();
    #pragma unroll
    for (int j = threadIdx.y; j < 32; j += 8)
        out[(size_t)(n0 + j) * K + k0 + threadIdx.x] = __float2half_rn(t[threadIdx.x][j]);
}

// ---------------- fp16 tensor-core GEMM --------------------------------------
// C[M,N] = act(A @ Bt^T + bias). A: [M,K] half. Bt: [N,K] half (K-major).
// SPLIT: rows [0,n0) expert0 / [n0,M) expert1 via blockIdx.z (boundary masked).
// GATHER: A row read via g_perm.  SCATTER: C row written via g_perm.
// OUT_HALF: C is half (intermediate layers); else float (final output).
template<bool RELU, bool GATHER, bool SCATTER, bool SPLIT, bool OUT_HALF>
__global__ void __launch_bounds__(256, 2)
moe_gemm_h(const __half* __restrict__ A,
           const __half* __restrict__ Bt0, const __half* __restrict__ Bt1,
           const float* __restrict__ bias0, const float* __restrict__ bias1,
           void* __restrict__ Cv, int M, int N, int K)
{
    const int n0 = SPLIT ? g_cnt0 : M;
    const int e  = SPLIT ? (int)blockIdx.z : 0;
    const int lo = (e == 0) ? 0  : n0;
    const int hi = (e == 0) ? n0 : M;
    const int row0 = blockIdx.y * BM;
    if (SPLIT && (row0 >= hi || row0 + BM <= lo)) return;
    const int col0 = blockIdx.x * BN;

    const __half* __restrict__ Bt   = (e == 0) ? Bt0   : Bt1;
    const float*  __restrict__ bias = (e == 0) ? bias0 : bias1;

    extern __shared__ char smem[];
    const uint32_t sbase = smem_u32(smem);

    const int tid   = threadIdx.x;
    const int warp  = tid >> 5;
    const int lane  = tid & 31;
    const int warpM = warp >> 2;      // 0..1 (64 rows)
    const int warpN = warp & 3;       // 0..3 (32 cols)
    const int g  = lane >> 2;         // 0..7
    const int tg = lane & 3;          // 0..3

    // ---- fill addressing: thread covers row r, granule pair b ----
    const int r = tid >> 1;           // 0..127
    const int b = tid & 1;            // 0..1
    const int mA = row0 + r;
    const bool vA = (!SPLIT) || (mA >= lo && mA < hi);
    const uint32_t aSz = vA ? 16u : 0u;
    const __half* aSrc = A + (size_t)(GATHER ? (vA ? g_perm[mA] : 0) : mA) * K + b * 16;
    const __half* bSrc = Bt + (size_t)(col0 + r) * K + b * 16;
    const uint32_t aDst = sbase + (uint32_t)(r * ROWB + b * 32);
    const uint32_t bDst = aDst + A_ST;

    const int nch = K / BK;

    // issue chunk c into its stage
    auto issue = [&](int c) {
        const uint32_t so = (uint32_t)((c % STAGES) * STAGE_BYTES);
        const __half* as = aSrc + c * BK;
        const __half* bs = bSrc + c * BK;
        CP_ASYNC16(aDst + so,      as,     aSz);
        CP_ASYNC16(aDst + so + 16, as + 8, aSz);
        CP_ASYNC16(bDst + so,      bs,     16u);
        CP_ASYNC16(bDst + so + 16, bs + 8, 16u);
        CP_COMMIT();
    };

    #pragma unroll
    for (int c = 0; c < STAGES - 1; c++) issue(c);

    float acc[4][4][4];
    #pragma unroll
    for (int mt = 0; mt < 4; mt++)
        #pragma unroll
        for (int nt = 0; nt < 4; nt++)
            #pragma unroll
            for (int i = 0; i < 4; i++) acc[mt][nt][i] = 0.0f;

    // per-warp ldmatrix base offsets (within a stage)
    const uint32_t aLd = sbase + (uint32_t)((warpM * 64 + (lane & 15)) * ROWB
                                            + (lane >> 4) * 16);
    const uint32_t bLd = sbase + A_ST
        + (uint32_t)((warpN * 32 + (lane & 7) + ((lane >> 4) << 3)) * ROWB
                     + ((lane >> 3) & 1) * 16);

    for (int i = 0; i < nch; i++) {
        CP_WAIT(STAGES - 2);
        __syncthreads();
        const uint32_t so = (uint32_t)((i % STAGES) * STAGE_BYTES);

        #pragma unroll
        for (int kh = 0; kh < 2; kh++) {
            uint32_t af[4][4], bf[2][4];
            #pragma unroll
            for (int mt = 0; mt < 4; mt++)
                LDSM_X4(af[mt][0], af[mt][1], af[mt][2], af[mt][3],
                        aLd + so + (uint32_t)(mt * 16 * ROWB + kh * 32));
            #pragma unroll
            for (int p = 0; p < 2; p++)
                LDSM_X4(bf[p][0], bf[p][1], bf[p][2], bf[p][3],
                        bLd + so + (uint32_t)(p * 16 * ROWB + kh * 32));
            #pragma unroll
            for (int mt = 0; mt < 4; mt++)
                #pragma unroll
                for (int nt = 0; nt < 4; nt++) {
                    uint32_t bb[2] = { bf[nt >> 1][(nt & 1) * 2],
                                       bf[nt >> 1][(nt & 1) * 2 + 1] };
                    MMA16816(acc[mt][nt], af[mt], bb);
                }
        }
        __syncthreads();   // all warps done reading this stage before refill
        if (i + STAGES - 1 < nch) issue(i + STAGES - 1);
        else                      CP_COMMIT();   // empty group keeps wait math uniform
    }

    // ---- epilogue ----
    #pragma unroll
    for (int mt = 0; mt < 4; mt++) {
        const int mBase = row0 + warpM * 64 + mt * 16 + g;
        #pragma unroll
        for (int nt = 0; nt < 4; nt++) {
            const int c = col0 + warpN * 32 + nt * 8 + 2 * tg;
            const float bv0 = bias[c];
            const float bv1 = bias[c + 1];
            #pragma unroll
            for (int half_i = 0; half_i < 2; half_i++) {
                const int m = mBase + half_i * 8;
                if (SPLIT && (m < lo || m >= hi)) continue;
                float v0 = acc[mt][nt][half_i * 2 + 0] + bv0;
                float v1 = acc[mt][nt][half_i * 2 + 1] + bv1;
                if (RELU) { v0 = fmaxf(v0, 0.f); v1 = fmaxf(v1, 0.f); }
                const int mo = SCATTER ? g_perm[m] : m;
                if (OUT_HALF) {
                    __half2 hv;
                    hv.x = __float2half_rn(v0);
                    hv.y = __float2half_rn(v1);
                    *(__half2*)((__half*)Cv + (size_t)mo * N + c) = hv;
                } else {
                    *(float2*)((float*)Cv + (size_t)mo * N + c) = make_float2(v0, v1);
                }
            }
        }
    }
}

// ---------------- launch ------------------------------------------------------
extern "C" void kernel_launch(void* const* d_in, const int* in_sizes, int n_in,
                              void* d_out, int out_size)
{
    const float* x     = (const float*)d_in[0];
    const int*   lang  = (const int*)  d_in[1];
    const float* W_de1 = (const float*)d_in[2];
    const float* b_de1 = (const float*)d_in[3];
    const float* W_de2 = (const float*)d_in[4];
    const float* b_de2 = (const float*)d_in[5];
    const float* W_nl1 = (const float*)d_in[6];
    const float* b_nl1 = (const float*)d_in[7];
    const float* W_nl2 = (const float*)d_in[8];
    const float* b_nl2 = (const float*)d_in[9];
    const float* W_d1  = (const float*)d_in[10];
    const float* b_d1  = (const float*)d_in[11];
    const float* W_d2  = (const float*)d_in[12];
    const float* b_d2  = (const float*)d_in[13];
    float* out = (float*)d_out;

    const int M = in_sizes[1];  // 32768

    __half *xh, *h1, *enc, *Wt_e1, *Wt_e2, *Wt_d1, *Wt_d2;
    cudaGetSymbolAddress((void**)&xh,    g_xh);
    cudaGetSymbolAddress((void**)&h1,    g_h1);
    cudaGetSymbolAddress((void**)&enc,   g_enc);
    cudaGetSymbolAddress((void**)&Wt_e1, g_Wt_e1);
    cudaGetSymbolAddress((void**)&Wt_e2, g_Wt_e2);
    cudaGetSymbolAddress((void**)&Wt_d1, g_Wt_d1);
    cudaGetSymbolAddress((void**)&Wt_d2, g_Wt_d2);

    cudaFuncSetAttribute(moe_gemm_h<true,  true,  false, true,  true >,
                         cudaFuncAttributeMaxDynamicSharedMemorySize, SMEM_DYN);
    cudaFuncSetAttribute(moe_gemm_h<false, false, false, true,  true >,
                         cudaFuncAttributeMaxDynamicSharedMemorySize, SMEM_DYN);
    cudaFuncSetAttribute(moe_gemm_h<true,  false, false, false, true >,
                         cudaFuncAttributeMaxDynamicSharedMemorySize, SMEM_DYN);
    cudaFuncSetAttribute(moe_gemm_h<false, false, true,  false, false>,
                         cudaFuncAttributeMaxDynamicSharedMemorySize, SMEM_DYN);

    init_counters_kernel<<<1, 1>>>();
    build_perm_kernel<<<(M + 255) / 256, 256>>>(lang, M);

    // x -> half
    {
        int n = M * D_IN;
        f2h_kernel<<<(n / 8 + 255) / 256, 256>>>(x, xh, n);
    }
    // weights -> transposed half [N][K]
    {
        dim3 blk(32, 8);
        transpose_h_kernel<<<dim3(HID / 32,  D_IN / 32), blk>>>(W_de1, Wt_e1, D_IN, HID);
        transpose_h_kernel<<<dim3(HID / 32,  D_IN / 32), blk>>>(W_nl1, Wt_e1 + (size_t)HID * D_IN, D_IN, HID);
        transpose_h_kernel<<<dim3(INTD / 32, HID / 32),  blk>>>(W_de2, Wt_e2, HID, INTD);
        transpose_h_kernel<<<dim3(INTD / 32, HID / 32),  blk>>>(W_nl2, Wt_e2 + (size_t)INTD * HID, HID, INTD);
        transpose_h_kernel<<<dim3(HID / 32,  INTD / 32), blk>>>(W_d1, Wt_d1, INTD, HID);
        transpose_h_kernel<<<dim3(D_IN / 32, HID / 32),  blk>>>(W_d2, Wt_d2, HID, D_IN);
    }

    // L1: h1 = relu(x[perm] @ W1_e + b1_e)   [split, gather]
    moe_gemm_h<true, true, false, true, true>
        <<<dim3(HID / BN, M / BM, 2), 256, SMEM_DYN>>>(
        xh, Wt_e1, Wt_e1 + (size_t)HID * D_IN, b_de1, b_nl1, h1, M, HID, D_IN);

    // L2: enc = h1 @ W2_e + b2_e             [split]
    moe_gemm_h<false, false, false, true, true>
        <<<dim3(INTD / BN, M / BM, 2), 256, SMEM_DYN>>>(
        h1, Wt_e2, Wt_e2 + (size_t)INTD * HID, b_de2, b_nl2, enc, M, INTD, HID);

    // L3: h1 = relu(enc @ W_d1 + b_d1)       [shared decoder]
    moe_gemm_h<true, false, false, false, true>
        <<<dim3(HID / BN, M / BM, 1), 256, SMEM_DYN>>>(
        enc, Wt_d1, Wt_d1, b_d1, b_d1, h1, M, HID, INTD);

    // L4: out[perm] = h1 @ W_d2 + b_d2       [scatter, f32 out]
    moe_gemm_h<false, false, true, false, false>
        <<<dim3(D_IN / BN, M / BM, 1), 256, SMEM_DYN>>>(
        h1, Wt_d2, Wt_d2, b_d2, b_d2, out, M, D_IN, HID);
}

// round 7
// speedup vs baseline: 2.2430x; 1.1552x over previous
#include <cuda_runtime.h>
#include <cuda_fp16.h>
#include <cstdint>
#include <cstddef>

// Problem shapes (fixed)
#define NROWS 32768
#define D_IN  1024
#define HID   1024
#define INTD  2048

// GEMM tiling: 128x256 CTA tile, 64x64 warp tile, K-chunk 32
#define BM 128
#define BN 256
#define BK 32               // halfs per chunk
#define STAGES 4
#define ROWB 80             // smem row stride bytes (64B data + 16B pad)
#define A_ST (BM * ROWB)    // 10240
#define B_ST (BN * ROWB)    // 20480
#define STAGE_BYTES (A_ST + B_ST)          // 30720
#define SMEM_DYN (STAGES * STAGE_BYTES)    // 122880

// ---------------- scratch (device globals: allocation-free rule) ------------
__device__ int    g_cnt0, g_cnt1;
__device__ int    g_perm[NROWS];
__device__ __half g_xh [(size_t)NROWS * D_IN];
__device__ __half g_h1 [(size_t)NROWS * HID];
__device__ __half g_enc[(size_t)NROWS * INTD];
// Pre-transposed half weights: [n][k] K-major
__device__ __half g_Wt_e1[(size_t)2 * HID  * D_IN];
__device__ __half g_Wt_e2[(size_t)2 * INTD * HID ];
__device__ __half g_Wt_d1[(size_t)HID  * INTD];
__device__ __half g_Wt_d2[(size_t)D_IN * HID ];

// ---------------- helpers ----------------------------------------------------
__device__ __forceinline__ uint32_t smem_u32(const void* p) {
    uint32_t a;
    asm("{ .reg .u64 t; cvta.to.shared.u64 t, %1; cvt.u32.u64 %0, t; }" : "=r"(a) : "l"(p));
    return a;
}

#define CP_ASYNC16(dst, src, sz) \
    asm volatile("cp.async.cg.shared.global [%0], [%1], 16, %2;" \
                 :: "r"(dst), "l"(src), "r"(sz) : "memory")
#define CP_COMMIT() asm volatile("cp.async.commit_group;" ::: "memory")
#define CP_WAIT(n)  asm volatile("cp.async.wait_group %0;" :: "n"(n) : "memory")

#define LDSM_X4(r0, r1, r2, r3, addr) \
    asm volatile("ldmatrix.sync.aligned.m8n8.x4.shared.b16 {%0,%1,%2,%3}, [%4];" \
                 : "=r"(r0), "=r"(r1), "=r"(r2), "=r"(r3) : "r"(addr))

#define MMA16816(d, a, b0, b1) \
    asm volatile("mma.sync.aligned.m16n8k16.row.col.f32.f16.f16.f32 " \
                 "{%0,%1,%2,%3}, {%4,%5,%6,%7}, {%8,%9}, {%0,%1,%2,%3};" \
                 : "+f"((d)[0]), "+f"((d)[1]), "+f"((d)[2]), "+f"((d)[3]) \
                 : "r"((a)[0]), "r"((a)[1]), "r"((a)[2]), "r"((a)[3]), \
                   "r"(b0), "r"(b1))

// ---------------- routing ----------------------------------------------------
__global__ void init_counters_kernel() { g_cnt0 = 0; g_cnt1 = 0; }

__global__ void build_perm_kernel(const int* __restrict__ lang, int n) {
    int i = blockIdx.x * blockDim.x + threadIdx.x;
    if (i < n) {
        if (lang[i] == 0) g_perm[atomicAdd(&g_cnt0, 1)] = i;
        else              g_perm[n - 1 - atomicAdd(&g_cnt1, 1)] = i;
    }
}

// ---------------- prep: f32 -> f16 convert / transpose -----------------------
__global__ void f2h_kernel(const float* __restrict__ in, __half* __restrict__ out,
                           int n) {
    int i = (blockIdx.x * blockDim.x + threadIdx.x) * 8;
    if (i < n) {
        float4 a = *(const float4*)(in + i);
        float4 b = *(const float4*)(in + i + 4);
        __half h[8];
        h[0] = __float2half_rn(a.x); h[1] = __float2half_rn(a.y);
        h[2] = __float2half_rn(a.z); h[3] = __float2half_rn(a.w);
        h[4] = __float2half_rn(b.x); h[5] = __float2half_rn(b.y);
        h[6] = __float2half_rn(b.z); h[7] = __float2half_rn(b.w);
        *(uint4*)(out + i) = *(const uint4*)h;
    }
}

// in: [K, N] row-major f32 -> out: [N, K] row-major half
__global__ void transpose_h_kernel(const float* __restrict__ in,
                                   __half* __restrict__ out, int K, int N) {
    __shared__ float t[32][33];
    int n0 = blockIdx.x * 32, k0 = blockIdx.y * 32;
    #pragma unroll
    for (int j = threadIdx.y; j < 32; j += 8)
        t[j][threadIdx.x] = in[(size_t)(k0 + j) * N + n0 + threadIdx.x];
    __syncthreads();
    #pragma unroll
    for (int j = threadIdx.y; j < 32; j += 8)
        out[(size_t)(n0 + j) * K + k0 + threadIdx.x] = __float2half_rn(t[threadIdx.x][j]);
}

// ---------------- fp16 tensor-core GEMM --------------------------------------
// C[M,N] = act(A @ Bt^T + bias). A: [M,K] half. Bt: [N,K] half (K-major).
// SPLIT: rows [0,n0) expert0 / [n0,M) expert1 via blockIdx.z (boundary masked).
// GATHER: A row read via g_perm.  SCATTER: C row written via g_perm.
// OUT_HALF: C is half (intermediate layers); else float (final output).
template<bool RELU, bool GATHER, bool SCATTER, bool SPLIT, bool OUT_HALF>
__global__ void __launch_bounds__(256, 1)
moe_gemm_h(const __half* __restrict__ A,
           const __half* __restrict__ Bt0, const __half* __restrict__ Bt1,
           const float* __restrict__ bias0, const float* __restrict__ bias1,
           void* __restrict__ Cv, int M, int N, int K)
{
    const int n0 = SPLIT ? g_cnt0 : M;
    const int e  = SPLIT ? (int)blockIdx.z : 0;
    const int lo = (e == 0) ? 0  : n0;
    const int hi = (e == 0) ? n0 : M;
    const int row0 = blockIdx.y * BM;
    if (SPLIT && (row0 >= hi || row0 + BM <= lo)) return;
    const int col0 = blockIdx.x * BN;

    const __half* __restrict__ Bt   = (e == 0) ? Bt0   : Bt1;
    const float*  __restrict__ bias = (e == 0) ? bias0 : bias1;

    extern __shared__ char smem[];
    const uint32_t sbase = smem_u32(smem);

    const int tid   = threadIdx.x;
    const int warp  = tid >> 5;
    const int lane  = tid & 31;
    const int warpM = warp >> 2;      // 0..1 (64 rows)
    const int warpN = warp & 3;       // 0..3 (64 cols)
    const int g  = lane >> 2;         // 0..7
    const int tg = lane & 3;          // 0..3

    // ---- fill addressing ----
    // A: 512 granule-slots (128 rows x 4 x 16B) -> 2 per thread
    // B: 1024 granule-slots (256 rows x 4 x 16B) -> 4 per thread
    const __half* aSrcp[2];
    uint32_t aDstp[2], aSz[2];
    #pragma unroll
    for (int s = 0; s < 2; s++) {
        int idx = tid + s * 256;
        int r = idx >> 2, gr = idx & 3;
        int m = row0 + r;
        bool v = (!SPLIT) || (m >= lo && m < hi);
        aSz[s]   = v ? 16u : 0u;
        aSrcp[s] = A + (size_t)(GATHER ? (v ? g_perm[m] : 0) : m) * K + gr * 8;
        aDstp[s] = sbase + (uint32_t)(r * ROWB + gr * 16);
    }
    const __half* bSrcp[4];
    uint32_t bDstp[4];
    #pragma unroll
    for (int s = 0; s < 4; s++) {
        int idx = tid + s * 256;
        int r = idx >> 2, gr = idx & 3;
        bSrcp[s] = Bt + (size_t)(col0 + r) * K + gr * 8;
        bDstp[s] = sbase + A_ST + (uint32_t)(r * ROWB + gr * 16);
    }

    const int nch = K / BK;

    auto issue = [&](int c) {
        const uint32_t so = (uint32_t)((c & (STAGES - 1)) * STAGE_BYTES);
        const int ko = c * BK;
        #pragma unroll
        for (int s = 0; s < 2; s++)
            CP_ASYNC16(aDstp[s] + so, aSrcp[s] + ko, aSz[s]);
        #pragma unroll
        for (int s = 0; s < 4; s++)
            CP_ASYNC16(bDstp[s] + so, bSrcp[s] + ko, 16u);
        CP_COMMIT();
    };

    #pragma unroll
    for (int c = 0; c < STAGES - 1; c++) issue(c);

    float acc[4][8][4];
    #pragma unroll
    for (int mt = 0; mt < 4; mt++)
        #pragma unroll
        for (int nt = 0; nt < 8; nt++)
            #pragma unroll
            for (int i = 0; i < 4; i++) acc[mt][nt][i] = 0.0f;

    // per-warp ldmatrix base offsets (within a stage)
    const uint32_t aLd = sbase + (uint32_t)((warpM * 64 + (lane & 15)) * ROWB
                                            + (lane >> 4) * 16);
    const uint32_t bLd = sbase + A_ST
        + (uint32_t)((warpN * 64 + (lane & 7) + ((lane >> 4) << 3)) * ROWB
                     + ((lane >> 3) & 1) * 16);

    for (int i = 0; i < nch; i++) {
        CP_WAIT(STAGES - 2);
        __syncthreads();
        // stage (i-1)%4 was fully consumed before every warp passed the
        // barrier above -> safe to refill it now (single barrier per iter).
        if (i + STAGES - 1 < nch) issue(i + STAGES - 1);

        const uint32_t so = (uint32_t)((i & (STAGES - 1)) * STAGE_BYTES);
        #pragma unroll
        for (int kh = 0; kh < 2; kh++) {
            uint32_t af[4][4], bf[4][4];
            #pragma unroll
            for (int mt = 0; mt < 4; mt++)
                LDSM_X4(af[mt][0], af[mt][1], af[mt][2], af[mt][3],
                        aLd + so + (uint32_t)(mt * 16 * ROWB + kh * 32));
            #pragma unroll
            for (int p = 0; p < 4; p++)
                LDSM_X4(bf[p][0], bf[p][1], bf[p][2], bf[p][3],
                        bLd + so + (uint32_t)(p * 16 * ROWB + kh * 32));
            #pragma unroll
            for (int mt = 0; mt < 4; mt++)
                #pragma unroll
                for (int nt = 0; nt < 8; nt++)
                    MMA16816(acc[mt][nt], af[mt],
                             bf[nt >> 1][(nt & 1) * 2],
                             bf[nt >> 1][(nt & 1) * 2 + 1]);
        }
    }

    // ---- epilogue ----
    #pragma unroll
    for (int mt = 0; mt < 4; mt++) {
        const int mBase = row0 + warpM * 64 + mt * 16 + g;
        #pragma unroll
        for (int nt = 0; nt < 8; nt++) {
            const int c = col0 + warpN * 64 + nt * 8 + 2 * tg;
            const float bv0 = bias[c];
            const float bv1 = bias[c + 1];
            #pragma unroll
            for (int half_i = 0; half_i < 2; half_i++) {
                const int m = mBase + half_i * 8;
                if (SPLIT && (m < lo || m >= hi)) continue;
                float v0 = acc[mt][nt][half_i * 2 + 0] + bv0;
                float v1 = acc[mt][nt][half_i * 2 + 1] + bv1;
                if (RELU) { v0 = fmaxf(v0, 0.f); v1 = fmaxf(v1, 0.f); }
                const int mo = SCATTER ? g_perm[m] : m;
                if (OUT_HALF) {
                    __half2 hv;
                    hv.x = __float2half_rn(v0);
                    hv.y = __float2half_rn(v1);
                    *(__half2*)((__half*)Cv + (size_t)mo * N + c) = hv;
                } else {
                    *(float2*)((float*)Cv + (size_t)mo * N + c) = make_float2(v0, v1);
                }
            }
        }
    }
}

// ---------------- launch ------------------------------------------------------
extern "C" void kernel_launch(void* const* d_in, const int* in_sizes, int n_in,
                              void* d_out, int out_size)
{
    const float* x     = (const float*)d_in[0];
    const int*   lang  = (const int*)  d_in[1];
    const float* W_de1 = (const float*)d_in[2];
    const float* b_de1 = (const float*)d_in[3];
    const float* W_de2 = (const float*)d_in[4];
    const float* b_de2 = (const float*)d_in[5];
    const float* W_nl1 = (const float*)d_in[6];
    const float* b_nl1 = (const float*)d_in[7];
    const float* W_nl2 = (const float*)d_in[8];
    const float* b_nl2 = (const float*)d_in[9];
    const float* W_d1  = (const float*)d_in[10];
    const float* b_d1  = (const float*)d_in[11];
    const float* W_d2  = (const float*)d_in[12];
    const float* b_d2  = (const float*)d_in[13];
    float* out = (float*)d_out;

    const int M = in_sizes[1];  // 32768

    __half *xh, *h1, *enc, *Wt_e1, *Wt_e2, *Wt_d1, *Wt_d2;
    cudaGetSymbolAddress((void**)&xh,    g_xh);
    cudaGetSymbolAddress((void**)&h1,    g_h1);
    cudaGetSymbolAddress((void**)&enc,   g_enc);
    cudaGetSymbolAddress((void**)&Wt_e1, g_Wt_e1);
    cudaGetSymbolAddress((void**)&Wt_e2, g_Wt_e2);
    cudaGetSymbolAddress((void**)&Wt_d1, g_Wt_d1);
    cudaGetSymbolAddress((void**)&Wt_d2, g_Wt_d2);

    cudaFuncSetAttribute(moe_gemm_h<true,  true,  false, true,  true >,
                         cudaFuncAttributeMaxDynamicSharedMemorySize, SMEM_DYN);
    cudaFuncSetAttribute(moe_gemm_h<false, false, false, true,  true >,
                         cudaFuncAttributeMaxDynamicSharedMemorySize, SMEM_DYN);
    cudaFuncSetAttribute(moe_gemm_h<true,  false, false, false, true >,
                         cudaFuncAttributeMaxDynamicSharedMemorySize, SMEM_DYN);
    cudaFuncSetAttribute(moe_gemm_h<false, false, true,  false, false>,
                         cudaFuncAttributeMaxDynamicSharedMemorySize, SMEM_DYN);

    init_counters_kernel<<<1, 1>>>();
    build_perm_kernel<<<(M + 255) / 256, 256>>>(lang, M);

    // x -> half
    {
        int n = M * D_IN;
        f2h_kernel<<<(n / 8 + 255) / 256, 256>>>(x, xh, n);
    }
    // weights -> transposed half [N][K]
    {
        dim3 blk(32, 8);
        transpose_h_kernel<<<dim3(HID / 32,  D_IN / 32), blk>>>(W_de1, Wt_e1, D_IN, HID);
        transpose_h_kernel<<<dim3(HID / 32,  D_IN / 32), blk>>>(W_nl1, Wt_e1 + (size_t)HID * D_IN, D_IN, HID);
        transpose_h_kernel<<<dim3(INTD / 32, HID / 32),  blk>>>(W_de2, Wt_e2, HID, INTD);
        transpose_h_kernel<<<dim3(INTD / 32, HID / 32),  blk>>>(W_nl2, Wt_e2 + (size_t)INTD * HID, HID, INTD);
        transpose_h_kernel<<<dim3(HID / 32,  INTD / 32), blk>>>(W_d1, Wt_d1, INTD, HID);
        transpose_h_kernel<<<dim3(D_IN / 32, HID / 32),  blk>>>(W_d2, Wt_d2, HID, D_IN);
    }

    // L1: h1 = relu(x[perm] @ W1_e + b1_e)   [split, gather]
    moe_gemm_h<true, true, false, true, true>
        <<<dim3(HID / BN, M / BM, 2), 256, SMEM_DYN>>>(
        xh, Wt_e1, Wt_e1 + (size_t)HID * D_IN, b_de1, b_nl1, h1, M, HID, D_IN);

    // L2: enc = h1 @ W2_e + b2_e             [split]
    moe_gemm_h<false, false, false, true, true>
        <<<dim3(INTD / BN, M / BM, 2), 256, SMEM_DYN>>>(
        h1, Wt_e2, Wt_e2 + (size_t)INTD * HID, b_de2, b_nl2, enc, M, INTD, HID);

    // L3: h1 = relu(enc @ W_d1 + b_d1)       [shared decoder]
    moe_gemm_h<true, false, false, false, true>
        <<<dim3(HID / BN, M / BM, 1), 256, SMEM_DYN>>>(
        enc, Wt_d1, Wt_d1, b_d1, b_d1, h1, M, HID, INTD);

    // L4: out[perm] = h1 @ W_d2 + b_d2       [scatter, f32 out]
    moe_gemm_h<false, false, true, false, false>
        <<<dim3(D_IN / BN, M / BM, 1), 256, SMEM_DYN>>>(
        h1, Wt_d2, Wt_d2, b_d2, b_d2, out, M, D_IN, HID);
}

// round 8
// speedup vs baseline: 2.9171x; 1.3006x over previous
#include <cuda_runtime.h>
#include <cuda_fp16.h>
#include <cstdint>
#include <cstddef>

// Problem shapes (fixed)
#define NROWS 32768
#define D_IN  1024
#define HID   1024
#define INTD  2048

// GEMM tiling: 128x256 CTA tile, 64x64 warp tile, K-chunk 64 halfs (128B rows)
#define BM 128
#define BN 256
#define BK 64
#define STAGES 3
#define ROWB 128                            // 64 halfs, no pad (XOR swizzle)
#define A_ST (BM * ROWB)                    // 16384
#define B_ST (BN * ROWB)                    // 32768
#define STAGE_BYTES (A_ST + B_ST)           // 49152
#define SMEM_DYN (STAGES * STAGE_BYTES)     // 147456

// ---------------- scratch (device globals: allocation-free rule) ------------
__device__ int    g_cnt0, g_cnt1;
__device__ int    g_perm[NROWS];
__device__ __half g_xh [(size_t)NROWS * D_IN];
__device__ __half g_h1 [(size_t)NROWS * HID];
__device__ __half g_enc[(size_t)NROWS * INTD];
// Pre-transposed half weights: [n][k] K-major
__device__ __half g_Wt_e1[(size_t)2 * HID  * D_IN];
__device__ __half g_Wt_e2[(size_t)2 * INTD * HID ];
__device__ __half g_Wt_d1[(size_t)HID  * INTD];
__device__ __half g_Wt_d2[(size_t)D_IN * HID ];

// ---------------- helpers ----------------------------------------------------
__device__ __forceinline__ uint32_t smem_u32(const void* p) {
    uint32_t a;
    asm("{ .reg .u64 t; cvta.to.shared.u64 t, %1; cvt.u32.u64 %0, t; }" : "=r"(a) : "l"(p));
    return a;
}

#define CP_ASYNC16(dst, src, sz) \
    asm volatile("cp.async.cg.shared.global [%0], [%1], 16, %2;" \
                 :: "r"(dst), "l"(src), "r"(sz) : "memory")
#define CP_COMMIT() asm volatile("cp.async.commit_group;" ::: "memory")
#define CP_WAIT(n)  asm volatile("cp.async.wait_group %0;" :: "n"(n) : "memory")

#define LDSM_X4(r0, r1, r2, r3, addr) \
    asm volatile("ldmatrix.sync.aligned.m8n8.x4.shared.b16 {%0,%1,%2,%3}, [%4];" \
                 : "=r"(r0), "=r"(r1), "=r"(r2), "=r"(r3) : "r"(addr))

#define MMA16816(d, a, b0, b1) \
    asm volatile("mma.sync.aligned.m16n8k16.row.col.f32.f16.f16.f32 " \
                 "{%0,%1,%2,%3}, {%4,%5,%6,%7}, {%8,%9}, {%0,%1,%2,%3};" \
                 : "+f"((d)[0]), "+f"((d)[1]), "+f"((d)[2]), "+f"((d)[3]) \
                 : "r"((a)[0]), "r"((a)[1]), "r"((a)[2]), "r"((a)[3]), \
                   "r"(b0), "r"(b1))

// ---------------- routing ----------------------------------------------------
__global__ void init_counters_kernel() { g_cnt0 = 0; g_cnt1 = 0; }

__global__ void build_perm_kernel(const int* __restrict__ lang, int n) {
    int i = blockIdx.x * blockDim.x + threadIdx.x;
    if (i < n) {
        if (lang[i] == 0) g_perm[atomicAdd(&g_cnt0, 1)] = i;
        else              g_perm[n - 1 - atomicAdd(&g_cnt1, 1)] = i;
    }
}

// ---------------- prep: f32 -> f16 convert / transpose -----------------------
__global__ void f2h_kernel(const float* __restrict__ in, __half* __restrict__ out,
                           int n) {
    int i = (blockIdx.x * blockDim.x + threadIdx.x) * 8;
    if (i < n) {
        float4 a = *(const float4*)(in + i);
        float4 b = *(const float4*)(in + i + 4);
        __half h[8];
        h[0] = __float2half_rn(a.x); h[1] = __float2half_rn(a.y);
        h[2] = __float2half_rn(a.z); h[3] = __float2half_rn(a.w);
        h[4] = __float2half_rn(b.x); h[5] = __float2half_rn(b.y);
        h[6] = __float2half_rn(b.z); h[7] = __float2half_rn(b.w);
        *(uint4*)(out + i) = *(const uint4*)h;
    }
}

// in: [K, N] row-major f32 -> out: [N, K] row-major half
__global__ void transpose_h_kernel(const float* __restrict__ in,
                                   __half* __restrict__ out, int K, int N) {
    __shared__ float t[32][33];
    int n0 = blockIdx.x * 32, k0 = blockIdx.y * 32;
    #pragma unroll
    for (int j = threadIdx.y; j < 32; j += 8)
        t[j][threadIdx.x] = in[(size_t)(k0 + j) * N + n0 + threadIdx.x];
    __syncthreads();
    #pragma unroll
    for (int j = threadIdx.y; j < 32; j += 8)
        out[(size_t)(n0 + j) * K + k0 + threadIdx.x] = __float2half_rn(t[threadIdx.x][j]);
}

// ---------------- fp16 tensor-core GEMM --------------------------------------
// C[M,N] = act(A @ Bt^T + bias). A: [M,K] half. Bt: [N,K] half (K-major).
// SMEM layout: 128B rows, XOR granule swizzle g' = g ^ (row & 7).
template<bool RELU, bool GATHER, bool SCATTER, bool SPLIT, bool OUT_HALF>
__global__ void __launch_bounds__(256, 1)
moe_gemm_h(const __half* __restrict__ A,
           const __half* __restrict__ Bt0, const __half* __restrict__ Bt1,
           const float* __restrict__ bias0, const float* __restrict__ bias1,
           void* __restrict__ Cv, int M, int N, int K)
{
    const int n0 = SPLIT ? g_cnt0 : M;
    const int e  = SPLIT ? (int)blockIdx.z : 0;
    const int lo = (e == 0) ? 0  : n0;
    const int hi = (e == 0) ? n0 : M;
    const int row0 = blockIdx.y * BM;
    if (SPLIT && (row0 >= hi || row0 + BM <= lo)) return;
    const int col0 = blockIdx.x * BN;

    const __half* __restrict__ Bt   = (e == 0) ? Bt0   : Bt1;
    const float*  __restrict__ bias = (e == 0) ? bias0 : bias1;

    extern __shared__ char smem[];
    const uint32_t sbase = smem_u32(smem);

    const int tid   = threadIdx.x;
    const int warp  = tid >> 5;
    const int lane  = tid & 31;
    const int warpM = warp >> 2;      // 0..1 (64 rows)
    const int warpN = warp & 3;       // 0..3 (64 cols)
    const int g  = lane >> 2;         // 0..7
    const int tg = lane & 3;          // 0..3

    // ---- fill addressing (granule = 16B = 8 halfs; 8 granules per row) ----
    // A: 128 rows x 8 granules = 1024 slots -> 4 per thread
    // B: 256 rows x 8 granules = 2048 slots -> 8 per thread
    const __half* aSrcp[4];
    uint32_t aDstp[4], aSz[4];
    #pragma unroll
    for (int s = 0; s < 4; s++) {
        int idx = tid + s * 256;
        int r = idx >> 3, gr = idx & 7;
        int m = row0 + r;
        bool v = (!SPLIT) || (m >= lo && m < hi);
        aSz[s]   = v ? 16u : 0u;
        aSrcp[s] = A + (size_t)(GATHER ? (v ? g_perm[m] : 0) : m) * K + gr * 8;
        aDstp[s] = sbase + (uint32_t)(r * ROWB + ((gr ^ (r & 7)) * 16));
    }
    const __half* bSrcp[8];
    uint32_t bDstp[8];
    #pragma unroll
    for (int s = 0; s < 8; s++) {
        int idx = tid + s * 256;
        int r = idx >> 3, gr = idx & 7;
        bSrcp[s] = Bt + (size_t)(col0 + r) * K + gr * 8;
        bDstp[s] = sbase + A_ST + (uint32_t)(r * ROWB + ((gr ^ (r & 7)) * 16));
    }

    const int nch = K / BK;

    auto issue = [&](int c) {
        const uint32_t so = (uint32_t)((c % STAGES) * STAGE_BYTES);
        const int ko = c * BK;
        #pragma unroll
        for (int s = 0; s < 4; s++)
            CP_ASYNC16(aDstp[s] + so, aSrcp[s] + ko, aSz[s]);
        #pragma unroll
        for (int s = 0; s < 8; s++)
            CP_ASYNC16(bDstp[s] + so, bSrcp[s] + ko, 16u);
        CP_COMMIT();
    };

    #pragma unroll
    for (int c = 0; c < STAGES - 1; c++) issue(c);

    float acc[4][8][4];
    #pragma unroll
    for (int mt = 0; mt < 4; mt++)
        #pragma unroll
        for (int nt = 0; nt < 8; nt++)
            #pragma unroll
            for (int i = 0; i < 4; i++) acc[mt][nt][i] = 0.0f;

    // per-warp ldmatrix row bases (byte offset of row within a stage) + masks
    // A tile mt: rows warpM*64 + mt*16 + (lane&15), chunk (lane>>4)
    uint32_t aRowOff[4]; int aRm[4];
    #pragma unroll
    for (int mt = 0; mt < 4; mt++) {
        int rr = warpM * 64 + mt * 16 + (lane & 15);
        aRowOff[mt] = sbase + (uint32_t)(rr * ROWB);
        aRm[mt] = rr & 7;
    }
    const int aChunk = lane >> 4;                 // 0..1
    // B tile p: rows warpN*64 + p*16 + (lane&7) + ((lane>>4)<<3), chunk (lane>>3)&1
    uint32_t bRowOff[4]; int bRm[4];
    #pragma unroll
    for (int p = 0; p < 4; p++) {
        int rr = warpN * 64 + p * 16 + (lane & 7) + ((lane >> 4) << 3);
        bRowOff[p] = sbase + A_ST + (uint32_t)(rr * ROWB);
        bRm[p] = rr & 7;
    }
    const int bChunk = (lane >> 3) & 1;           // 0..1

    for (int i = 0; i < nch; i++) {
        CP_WAIT(STAGES - 2);
        __syncthreads();
        if (i + STAGES - 1 < nch) issue(i + STAGES - 1);

        const uint32_t so = (uint32_t)((i % STAGES) * STAGE_BYTES);
        #pragma unroll
        for (int kh = 0; kh < BK / 16; kh++) {    // 4 k-steps of 16
            uint32_t af[4][4], bf[4][4];
            #pragma unroll
            for (int mt = 0; mt < 4; mt++) {
                uint32_t ad = aRowOff[mt] + so
                    + (uint32_t)(((kh * 2 + aChunk) ^ aRm[mt]) * 16);
                LDSM_X4(af[mt][0], af[mt][1], af[mt][2], af[mt][3], ad);
            }
            #pragma unroll
            for (int p = 0; p < 4; p++) {
                uint32_t bd = bRowOff[p] + so
                    + (uint32_t)(((kh * 2 + bChunk) ^ bRm[p]) * 16);
                LDSM_X4(bf[p][0], bf[p][1], bf[p][2], bf[p][3], bd);
            }
            #pragma unroll
            for (int mt = 0; mt < 4; mt++)
                #pragma unroll
                for (int nt = 0; nt < 8; nt++)
                    MMA16816(acc[mt][nt], af[mt],
                             bf[nt >> 1][(nt & 1) * 2],
                             bf[nt >> 1][(nt & 1) * 2 + 1]);
        }
    }

    // ---- epilogue ----
    #pragma unroll
    for (int mt = 0; mt < 4; mt++) {
        const int mBase = row0 + warpM * 64 + mt * 16 + g;
        #pragma unroll
        for (int nt = 0; nt < 8; nt++) {
            const int c = col0 + warpN * 64 + nt * 8 + 2 * tg;
            const float bv0 = bias[c];
            const float bv1 = bias[c + 1];
            #pragma unroll
            for (int half_i = 0; half_i < 2; half_i++) {
                const int m = mBase + half_i * 8;
                if (SPLIT && (m < lo || m >= hi)) continue;
                float v0 = acc[mt][nt][half_i * 2 + 0] + bv0;
                float v1 = acc[mt][nt][half_i * 2 + 1] + bv1;
                if (RELU) { v0 = fmaxf(v0, 0.f); v1 = fmaxf(v1, 0.f); }
                const int mo = SCATTER ? g_perm[m] : m;
                if (OUT_HALF) {
                    __half2 hv;
                    hv.x = __float2half_rn(v0);
                    hv.y = __float2half_rn(v1);
                    *(__half2*)((__half*)Cv + (size_t)mo * N + c) = hv;
                } else {
                    *(float2*)((float*)Cv + (size_t)mo * N + c) = make_float2(v0, v1);
                }
            }
        }
    }
}

// ---------------- launch ------------------------------------------------------
extern "C" void kernel_launch(void* const* d_in, const int* in_sizes, int n_in,
                              void* d_out, int out_size)
{
    const float* x     = (const float*)d_in[0];
    const int*   lang  = (const int*)  d_in[1];
    const float* W_de1 = (const float*)d_in[2];
    const float* b_de1 = (const float*)d_in[3];
    const float* W_de2 = (const float*)d_in[4];
    const float* b_de2 = (const float*)d_in[5];
    const float* W_nl1 = (const float*)d_in[6];
    const float* b_nl1 = (const float*)d_in[7];
    const float* W_nl2 = (const float*)d_in[8];
    const float* b_nl2 = (const float*)d_in[9];
    const float* W_d1  = (const float*)d_in[10];
    const float* b_d1  = (const float*)d_in[11];
    const float* W_d2  = (const float*)d_in[12];
    const float* b_d2  = (const float*)d_in[13];
    float* out = (float*)d_out;

    const int M = in_sizes[1];  // 32768

    __half *xh, *h1, *enc, *Wt_e1, *Wt_e2, *Wt_d1, *Wt_d2;
    cudaGetSymbolAddress((void**)&xh,    g_xh);
    cudaGetSymbolAddress((void**)&h1,    g_h1);
    cudaGetSymbolAddress((void**)&enc,   g_enc);
    cudaGetSymbolAddress((void**)&Wt_e1, g_Wt_e1);
    cudaGetSymbolAddress((void**)&Wt_e2, g_Wt_e2);
    cudaGetSymbolAddress((void**)&Wt_d1, g_Wt_d1);
    cudaGetSymbolAddress((void**)&Wt_d2, g_Wt_d2);

    cudaFuncSetAttribute(moe_gemm_h<true,  true,  false, true,  true >,
                         cudaFuncAttributeMaxDynamicSharedMemorySize, SMEM_DYN);
    cudaFuncSetAttribute(moe_gemm_h<false, false, false, true,  true >,
                         cudaFuncAttributeMaxDynamicSharedMemorySize, SMEM_DYN);
    cudaFuncSetAttribute(moe_gemm_h<true,  false, false, false, true >,
                         cudaFuncAttributeMaxDynamicSharedMemorySize, SMEM_DYN);
    cudaFuncSetAttribute(moe_gemm_h<false, false, true,  false, false>,
                         cudaFuncAttributeMaxDynamicSharedMemorySize, SMEM_DYN);

    init_counters_kernel<<<1, 1>>>();
    build_perm_kernel<<<(M + 255) / 256, 256>>>(lang, M);

    // x -> half
    {
        int n = M * D_IN;
        f2h_kernel<<<(n / 8 + 255) / 256, 256>>>(x, xh, n);
    }
    // weights -> transposed half [N][K]
    {
        dim3 blk(32, 8);
        transpose_h_kernel<<<dim3(HID / 32,  D_IN / 32), blk>>>(W_de1, Wt_e1, D_IN, HID);
        transpose_h_kernel<<<dim3(HID / 32,  D_IN / 32), blk>>>(W_nl1, Wt_e1 + (size_t)HID * D_IN, D_IN, HID);
        transpose_h_kernel<<<dim3(INTD / 32, HID / 32),  blk>>>(W_de2, Wt_e2, HID, INTD);
        transpose_h_kernel<<<dim3(INTD / 32, HID / 32),  blk>>>(W_nl2, Wt_e2 + (size_t)INTD * HID, HID, INTD);
        transpose_h_kernel<<<dim3(HID / 32,  INTD / 32), blk>>>(W_d1, Wt_d1, INTD, HID);
        transpose_h_kernel<<<dim3(D_IN / 32, HID / 32),  blk>>>(W_d2, Wt_d2, HID, D_IN);
    }

    // L1: h1 = relu(x[perm] @ W1_e + b1_e)   [split, gather]
    moe_gemm_h<true, true, false, true, true>
        <<<dim3(HID / BN, M / BM, 2), 256, SMEM_DYN>>>(
        xh, Wt_e1, Wt_e1 + (size_t)HID * D_IN, b_de1, b_nl1, h1, M, HID, D_IN);

    // L2: enc = h1 @ W2_e + b2_e             [split]
    moe_gemm_h<false, false, false, true, true>
        <<<dim3(INTD / BN, M / BM, 2), 256, SMEM_DYN>>>(
        h1, Wt_e2, Wt_e2 + (size_t)INTD * HID, b_de2, b_nl2, enc, M, INTD, HID);

    // L3: h1 = relu(enc @ W_d1 + b_d1)       [shared decoder]
    moe_gemm_h<true, false, false, false, true>
        <<<dim3(HID / BN, M / BM, 1), 256, SMEM_DYN>>>(
        enc, Wt_d1, Wt_d1, b_d1, b_d1, h1, M, HID, INTD);

    // L4: out[perm] = h1 @ W_d2 + b_d2       [scatter, f32 out]
    moe_gemm_h<false, false, true, false, false>
        <<<dim3(D_IN / BN, M / BM, 1), 256, SMEM_DYN>>>(
        h1, Wt_d2, Wt_d2, b_d2, b_d2, out, M, D_IN, HID);
}

// round 9
// speedup vs baseline: 2.9376x; 1.0070x over previous
#include <cuda_runtime.h>
#include <cuda_fp16.h>
#include <cstdint>
#include <cstddef>

// Problem shapes (fixed)
#define NROWS 32768
#define D_IN  1024
#define HID   1024
#define INTD  2048

// GEMM tiling: 128x256 CTA tile, 64x64 warp tile, K-chunk 64 halfs (128B rows)
#define BM 128
#define BN 256
#define BK 64
#define STAGES 4
#define ROWB 128                            // 64 halfs, no pad (XOR swizzle)
#define A_ST (BM * ROWB)                    // 16384
#define B_ST (BN * ROWB)                    // 32768
#define STAGE_BYTES (A_ST + B_ST)           // 49152
#define SMEM_DYN (STAGES * STAGE_BYTES)     // 196608

// ---------------- scratch (device globals: allocation-free rule) ------------
__device__ int    g_cnt0, g_cnt1;
__device__ int    g_perm[NROWS];
__device__ __half g_xh [(size_t)NROWS * D_IN];
__device__ __half g_h1 [(size_t)NROWS * HID];
__device__ __half g_enc[(size_t)NROWS * INTD];
// Pre-transposed half weights: [n][k] K-major
__device__ __half g_Wt_e1[(size_t)2 * HID  * D_IN];
__device__ __half g_Wt_e2[(size_t)2 * INTD * HID ];
__device__ __half g_Wt_d1[(size_t)HID  * INTD];
__device__ __half g_Wt_d2[(size_t)D_IN * HID ];

// ---------------- helpers ----------------------------------------------------
__device__ __forceinline__ uint32_t smem_u32(const void* p) {
    uint32_t a;
    asm("{ .reg .u64 t; cvta.to.shared.u64 t, %1; cvt.u32.u64 %0, t; }" : "=r"(a) : "l"(p));
    return a;
}

#define CP_ASYNC16(dst, src, sz) \
    asm volatile("cp.async.cg.shared.global [%0], [%1], 16, %2;" \
                 :: "r"(dst), "l"(src), "r"(sz) : "memory")
#define CP_COMMIT() asm volatile("cp.async.commit_group;" ::: "memory")
#define CP_WAIT(n)  asm volatile("cp.async.wait_group %0;" :: "n"(n) : "memory")

#define LDSM_X4(r0, r1, r2, r3, addr) \
    asm volatile("ldmatrix.sync.aligned.m8n8.x4.shared.b16 {%0,%1,%2,%3}, [%4];" \
                 : "=r"(r0), "=r"(r1), "=r"(r2), "=r"(r3) : "r"(addr))

#define MMA16816(d, a, b0, b1) \
    asm volatile("mma.sync.aligned.m16n8k16.row.col.f32.f16.f16.f32 " \
                 "{%0,%1,%2,%3}, {%4,%5,%6,%7}, {%8,%9}, {%0,%1,%2,%3};" \
                 : "+f"((d)[0]), "+f"((d)[1]), "+f"((d)[2]), "+f"((d)[3]) \
                 : "r"((a)[0]), "r"((a)[1]), "r"((a)[2]), "r"((a)[3]), \
                   "r"(b0), "r"(b1))

// ---------------- routing ----------------------------------------------------
__global__ void init_counters_kernel() { g_cnt0 = 0; g_cnt1 = 0; }

__global__ void build_perm_kernel(const int* __restrict__ lang, int n) {
    int i = blockIdx.x * blockDim.x + threadIdx.x;
    if (i < n) {
        if (lang[i] == 0) g_perm[atomicAdd(&g_cnt0, 1)] = i;
        else              g_perm[n - 1 - atomicAdd(&g_cnt1, 1)] = i;
    }
}

// ---------------- prep: f32 -> f16 convert / transpose -----------------------
__global__ void f2h_kernel(const float* __restrict__ in, __half* __restrict__ out,
                           int n) {
    int i = (blockIdx.x * blockDim.x + threadIdx.x) * 8;
    if (i < n) {
        float4 a = *(const float4*)(in + i);
        float4 b = *(const float4*)(in + i + 4);
        __half h[8];
        h[0] = __float2half_rn(a.x); h[1] = __float2half_rn(a.y);
        h[2] = __float2half_rn(a.z); h[3] = __float2half_rn(a.w);
        h[4] = __float2half_rn(b.x); h[5] = __float2half_rn(b.y);
        h[6] = __float2half_rn(b.z); h[7] = __float2half_rn(b.w);
        *(uint4*)(out + i) = *(const uint4*)h;
    }
}

// in: [K, N] row-major f32 -> out: [N, K] row-major half
__global__ void transpose_h_kernel(const float* __restrict__ in,
                                   __half* __restrict__ out, int K, int N) {
    __shared__ float t[32][33];
    int n0 = blockIdx.x * 32, k0 = blockIdx.y * 32;
    #pragma unroll
    for (int j = threadIdx.y; j < 32; j += 8)
        t[j][threadIdx.x] = in[(size_t)(k0 + j) * N + n0 + threadIdx.x];
    __syncthreads();
    #pragma unroll
    for (int j = threadIdx.y; j < 32; j += 8)
        out[(size_t)(n0 + j) * K + k0 + threadIdx.x] = __float2half_rn(t[threadIdx.x][j]);
}

// ---------------- fp16 tensor-core GEMM --------------------------------------
// C[M,N] = act(A @ Bt^T + bias). A: [M,K] half. Bt: [N,K] half (K-major).
// SMEM: 128B rows, XOR granule swizzle g' = g ^ (row & 7).
// Mainloop: 4-stage cp.async pipeline + register double-buffered fragments.
template<bool RELU, bool GATHER, bool SCATTER, bool SPLIT, bool OUT_HALF>
__global__ void __launch_bounds__(256, 1)
moe_gemm_h(const __half* __restrict__ A,
           const __half* __restrict__ Bt0, const __half* __restrict__ Bt1,
           const float* __restrict__ bias0, const float* __restrict__ bias1,
           void* __restrict__ Cv, int M, int N, int K)
{
    const int n0 = SPLIT ? g_cnt0 : M;
    const int e  = SPLIT ? (int)blockIdx.z : 0;
    const int lo = (e == 0) ? 0  : n0;
    const int hi = (e == 0) ? n0 : M;
    const int row0 = blockIdx.y * BM;
    if (SPLIT && (row0 >= hi || row0 + BM <= lo)) return;
    const int col0 = blockIdx.x * BN;

    const __half* __restrict__ Bt   = (e == 0) ? Bt0   : Bt1;
    const float*  __restrict__ bias = (e == 0) ? bias0 : bias1;

    extern __shared__ char smem[];
    const uint32_t sbase = smem_u32(smem);

    const int tid   = threadIdx.x;
    const int warp  = tid >> 5;
    const int lane  = tid & 31;
    const int warpM = warp >> 2;      // 0..1 (64 rows)
    const int warpN = warp & 3;       // 0..3 (64 cols)
    const int g  = lane >> 2;         // 0..7
    const int tg = lane & 3;          // 0..3

    // ---- fill addressing (granule = 16B = 8 halfs; 8 granules per row) ----
    const __half* aSrcp[4];
    uint32_t aDstp[4], aSz[4];
    #pragma unroll
    for (int s = 0; s < 4; s++) {
        int idx = tid + s * 256;
        int r = idx >> 3, gr = idx & 7;
        int m = row0 + r;
        bool v = (!SPLIT) || (m >= lo && m < hi);
        aSz[s]   = v ? 16u : 0u;
        aSrcp[s] = A + (size_t)(GATHER ? (v ? g_perm[m] : 0) : m) * K + gr * 8;
        aDstp[s] = sbase + (uint32_t)(r * ROWB + ((gr ^ (r & 7)) * 16));
    }
    const __half* bSrcp[8];
    uint32_t bDstp[8];
    #pragma unroll
    for (int s = 0; s < 8; s++) {
        int idx = tid + s * 256;
        int r = idx >> 3, gr = idx & 7;
        bSrcp[s] = Bt + (size_t)(col0 + r) * K + gr * 8;
        bDstp[s] = sbase + A_ST + (uint32_t)(r * ROWB + ((gr ^ (r & 7)) * 16));
    }

    const int nch = K / BK;

    auto issue = [&](int c) {
        const uint32_t so = (uint32_t)((c % STAGES) * STAGE_BYTES);
        const int ko = c * BK;
        #pragma unroll
        for (int s = 0; s < 4; s++)
            CP_ASYNC16(aDstp[s] + so, aSrcp[s] + ko, aSz[s]);
        #pragma unroll
        for (int s = 0; s < 8; s++)
            CP_ASYNC16(bDstp[s] + so, bSrcp[s] + ko, 16u);
        CP_COMMIT();
    };

    #pragma unroll
    for (int c = 0; c < STAGES - 1; c++) issue(c);

    float acc[4][8][4];
    #pragma unroll
    for (int mt = 0; mt < 4; mt++)
        #pragma unroll
        for (int nt = 0; nt < 8; nt++)
            #pragma unroll
            for (int i = 0; i < 4; i++) acc[mt][nt][i] = 0.0f;

    // per-warp ldmatrix row bases + swizzle masks
    uint32_t aRowOff[4]; int aRm[4];
    #pragma unroll
    for (int mt = 0; mt < 4; mt++) {
        int rr = warpM * 64 + mt * 16 + (lane & 15);
        aRowOff[mt] = sbase + (uint32_t)(rr * ROWB);
        aRm[mt] = rr & 7;
    }
    const int aChunk = lane >> 4;                 // 0..1
    uint32_t bRowOff[4]; int bRm[4];
    #pragma unroll
    for (int p = 0; p < 4; p++) {
        int rr = warpN * 64 + p * 16 + (lane & 7) + ((lane >> 4) << 3);
        bRowOff[p] = sbase + A_ST + (uint32_t)(rr * ROWB);
        bRm[p] = rr & 7;
    }
    const int bChunk = (lane >> 3) & 1;           // 0..1

    uint32_t af[2][4][4], bf[2][4][4];

    auto load_frags = [&](int buf, uint32_t so, int kh) {
        #pragma unroll
        for (int mt = 0; mt < 4; mt++) {
            uint32_t ad = aRowOff[mt] + so
                + (uint32_t)(((kh * 2 + aChunk) ^ aRm[mt]) * 16);
            LDSM_X4(af[buf][mt][0], af[buf][mt][1], af[buf][mt][2], af[buf][mt][3], ad);
        }
        #pragma unroll
        for (int p = 0; p < 4; p++) {
            uint32_t bd = bRowOff[p] + so
                + (uint32_t)(((kh * 2 + bChunk) ^ bRm[p]) * 16);
            LDSM_X4(bf[buf][p][0], bf[buf][p][1], bf[buf][p][2], bf[buf][p][3], bd);
        }
    };

    for (int i = 0; i < nch; i++) {
        CP_WAIT(STAGES - 2);
        __syncthreads();
        if (i + STAGES - 1 < nch) issue(i + STAGES - 1);

        const uint32_t so = (uint32_t)((i % STAGES) * STAGE_BYTES);
        load_frags(0, so, 0);
        #pragma unroll
        for (int kh = 0; kh < BK / 16; kh++) {    // 4 k-steps of 16
            const int cur = kh & 1;
            if (kh + 1 < BK / 16) load_frags(cur ^ 1, so, kh + 1);
            #pragma unroll
            for (int mt = 0; mt < 4; mt++)
                #pragma unroll
                for (int nt = 0; nt < 8; nt++)
                    MMA16816(acc[mt][nt], af[cur][mt],
                             bf[cur][nt >> 1][(nt & 1) * 2],
                             bf[cur][nt >> 1][(nt & 1) * 2 + 1]);
        }
    }

    // ---- epilogue ----
    #pragma unroll
    for (int mt = 0; mt < 4; mt++) {
        const int mBase = row0 + warpM * 64 + mt * 16 + g;
        #pragma unroll
        for (int nt = 0; nt < 8; nt++) {
            const int c = col0 + warpN * 64 + nt * 8 + 2 * tg;
            const float bv0 = bias[c];
            const float bv1 = bias[c + 1];
            #pragma unroll
            for (int half_i = 0; half_i < 2; half_i++) {
                const int m = mBase + half_i * 8;
                if (SPLIT && (m < lo || m >= hi)) continue;
                float v0 = acc[mt][nt][half_i * 2 + 0] + bv0;
                float v1 = acc[mt][nt][half_i * 2 + 1] + bv1;
                if (RELU) { v0 = fmaxf(v0, 0.f); v1 = fmaxf(v1, 0.f); }
                const int mo = SCATTER ? g_perm[m] : m;
                if (OUT_HALF) {
                    __half2 hv;
                    hv.x = __float2half_rn(v0);
                    hv.y = __float2half_rn(v1);
                    *(__half2*)((__half*)Cv + (size_t)mo * N + c) = hv;
                } else {
                    *(float2*)((float*)Cv + (size_t)mo * N + c) = make_float2(v0, v1);
                }
            }
        }
    }
}

// ---------------- launch ------------------------------------------------------
extern "C" void kernel_launch(void* const* d_in, const int* in_sizes, int n_in,
                              void* d_out, int out_size)
{
    const float* x     = (const float*)d_in[0];
    const int*   lang  = (const int*)  d_in[1];
    const float* W_de1 = (const float*)d_in[2];
    const float* b_de1 = (const float*)d_in[3];
    const float* W_de2 = (const float*)d_in[4];
    const float* b_de2 = (const float*)d_in[5];
    const float* W_nl1 = (const float*)d_in[6];
    const float* b_nl1 = (const float*)d_in[7];
    const float* W_nl2 = (const float*)d_in[8];
    const float* b_nl2 = (const float*)d_in[9];
    const float* W_d1  = (const float*)d_in[10];
    const float* b_d1  = (const float*)d_in[11];
    const float* W_d2  = (const float*)d_in[12];
    const float* b_d2  = (const float*)d_in[13];
    float* out = (float*)d_out;

    const int M = in_sizes[1];  // 32768

    __half *xh, *h1, *enc, *Wt_e1, *Wt_e2, *Wt_d1, *Wt_d2;
    cudaGetSymbolAddress((void**)&xh,    g_xh);
    cudaGetSymbolAddress((void**)&h1,    g_h1);
    cudaGetSymbolAddress((void**)&enc,   g_enc);
    cudaGetSymbolAddress((void**)&Wt_e1, g_Wt_e1);
    cudaGetSymbolAddress((void**)&Wt_e2, g_Wt_e2);
    cudaGetSymbolAddress((void**)&Wt_d1, g_Wt_d1);
    cudaGetSymbolAddress((void**)&Wt_d2, g_Wt_d2);

    cudaFuncSetAttribute(moe_gemm_h<true,  true,  false, true,  true >,
                         cudaFuncAttributeMaxDynamicSharedMemorySize, SMEM_DYN);
    cudaFuncSetAttribute(moe_gemm_h<false, false, false, true,  true >,
                         cudaFuncAttributeMaxDynamicSharedMemorySize, SMEM_DYN);
    cudaFuncSetAttribute(moe_gemm_h<true,  false, false, false, true >,
                         cudaFuncAttributeMaxDynamicSharedMemorySize, SMEM_DYN);
    cudaFuncSetAttribute(moe_gemm_h<false, false, true,  false, false>,
                         cudaFuncAttributeMaxDynamicSharedMemorySize, SMEM_DYN);

    init_counters_kernel<<<1, 1>>>();
    build_perm_kernel<<<(M + 255) / 256, 256>>>(lang, M);

    // x -> half
    {
        int n = M * D_IN;
        f2h_kernel<<<(n / 8 + 255) / 256, 256>>>(x, xh, n);
    }
    // weights -> transposed half [N][K]
    {
        dim3 blk(32, 8);
        transpose_h_kernel<<<dim3(HID / 32,  D_IN / 32), blk>>>(W_de1, Wt_e1, D_IN, HID);
        transpose_h_kernel<<<dim3(HID / 32,  D_IN / 32), blk>>>(W_nl1, Wt_e1 + (size_t)HID * D_IN, D_IN, HID);
        transpose_h_kernel<<<dim3(INTD / 32, HID / 32),  blk>>>(W_de2, Wt_e2, HID, INTD);
        transpose_h_kernel<<<dim3(INTD / 32, HID / 32),  blk>>>(W_nl2, Wt_e2 + (size_t)INTD * HID, HID, INTD);
        transpose_h_kernel<<<dim3(HID / 32,  INTD / 32), blk>>>(W_d1, Wt_d1, INTD, HID);
        transpose_h_kernel<<<dim3(D_IN / 32, HID / 32),  blk>>>(W_d2, Wt_d2, HID, D_IN);
    }

    // L1: h1 = relu(x[perm] @ W1_e + b1_e)   [split, gather]
    moe_gemm_h<true, true, false, true, true>
        <<<dim3(HID / BN, M / BM, 2), 256, SMEM_DYN>>>(
        xh, Wt_e1, Wt_e1 + (size_t)HID * D_IN, b_de1, b_nl1, h1, M, HID, D_IN);

    // L2: enc = h1 @ W2_e + b2_e             [split]
    moe_gemm_h<false, false, false, true, true>
        <<<dim3(INTD / BN, M / BM, 2), 256, SMEM_DYN>>>(
        h1, Wt_e2, Wt_e2 + (size_t)INTD * HID, b_de2, b_nl2, enc, M, INTD, HID);

    // L3: h1 = relu(enc @ W_d1 + b_d1)       [shared decoder]
    moe_gemm_h<true, false, false, false, true>
        <<<dim3(HID / BN, M / BM, 1), 256, SMEM_DYN>>>(
        enc, Wt_d1, Wt_d1, b_d1, b_d1, h1, M, HID, INTD);

    // L4: out[perm] = h1 @ W_d2 + b_d2       [scatter, f32 out]
    moe_gemm_h<false, false, true, false, false>
        <<<dim3(D_IN / BN, M / BM, 1), 256, SMEM_DYN>>>(
        h1, Wt_d2, Wt_d2, b_d2, b_d2, out, M, D_IN, HID);
}

// round 10
// speedup vs baseline: 2.9820x; 1.0151x over previous
#include <cuda_runtime.h>
#include <cuda_fp16.h>
#include <cstdint>
#include <cstddef>

// Problem shapes (fixed)
#define NROWS 32768
#define D_IN  1024
#define HID   1024
#define INTD  2048

// GEMM tiling: 128x256 CTA tile, 64x64 warp tile, K-chunk 64 halfs (128B rows)
#define BM 128
#define BN 256
#define BK 64
#define STAGES 4
#define ROWB 128                            // 64 halfs, no pad (XOR swizzle)
#define A_ST (BM * ROWB)                    // 16384
#define B_ST (BN * ROWB)                    // 32768
#define STAGE_BYTES (A_ST + B_ST)           // 49152
#define SMEM_DYN (STAGES * STAGE_BYTES)     // 196608

// ---------------- scratch (device globals: allocation-free rule) ------------
__device__ int    g_cnt0, g_cnt1;
__device__ int    g_perm[NROWS];
__device__ __half g_xh [(size_t)NROWS * D_IN];
__device__ __half g_h1 [(size_t)NROWS * HID];
__device__ __half g_enc[(size_t)NROWS * INTD];
// Pre-transposed half weights: [n][k] K-major
__device__ __half g_Wt_e1[(size_t)2 * HID  * D_IN];
__device__ __half g_Wt_e2[(size_t)2 * INTD * HID ];
__device__ __half g_Wt_d1[(size_t)HID  * INTD];
__device__ __half g_Wt_d2[(size_t)D_IN * HID ];

// ---------------- helpers ----------------------------------------------------
__device__ __forceinline__ uint32_t smem_u32(const void* p) {
    uint32_t a;
    asm("{ .reg .u64 t; cvta.to.shared.u64 t, %1; cvt.u32.u64 %0, t; }" : "=r"(a) : "l"(p));
    return a;
}

#define CP_ASYNC16(dst, src, sz) \
    asm volatile("cp.async.cg.shared.global [%0], [%1], 16, %2;" \
                 :: "r"(dst), "l"(src), "r"(sz) : "memory")
#define CP_COMMIT() asm volatile("cp.async.commit_group;" ::: "memory")
#define CP_WAIT(n)  asm volatile("cp.async.wait_group %0;" :: "n"(n) : "memory")

#define LDSM_X4(r0, r1, r2, r3, addr) \
    asm volatile("ldmatrix.sync.aligned.m8n8.x4.shared.b16 {%0,%1,%2,%3}, [%4];" \
                 : "=r"(r0), "=r"(r1), "=r"(r2), "=r"(r3) : "r"(addr))

#define MMA16816(d, a, b0, b1) \
    asm volatile("mma.sync.aligned.m16n8k16.row.col.f32.f16.f16.f32 " \
                 "{%0,%1,%2,%3}, {%4,%5,%6,%7}, {%8,%9}, {%0,%1,%2,%3};" \
                 : "+f"((d)[0]), "+f"((d)[1]), "+f"((d)[2]), "+f"((d)[3]) \
                 : "r"((a)[0]), "r"((a)[1]), "r"((a)[2]), "r"((a)[3]), \
                   "r"(b0), "r"(b1))

// ---------------- routing ----------------------------------------------------
__global__ void init_counters_kernel() { g_cnt0 = 0; g_cnt1 = 0; }

__global__ void build_perm_kernel(const int* __restrict__ lang, int n) {
    int i = blockIdx.x * blockDim.x + threadIdx.x;
    if (i < n) {
        if (lang[i] == 0) g_perm[atomicAdd(&g_cnt0, 1)] = i;
        else              g_perm[n - 1 - atomicAdd(&g_cnt1, 1)] = i;
    }
}

// ---------------- prep: f32 -> f16 convert -----------------------------------
__global__ void f2h_kernel(const float* __restrict__ in, __half* __restrict__ out,
                           int n) {
    int i = (blockIdx.x * blockDim.x + threadIdx.x) * 8;
    if (i < n) {
        float4 a = *(const float4*)(in + i);
        float4 b = *(const float4*)(in + i + 4);
        __half h[8];
        h[0] = __float2half_rn(a.x); h[1] = __float2half_rn(a.y);
        h[2] = __float2half_rn(a.z); h[3] = __float2half_rn(a.w);
        h[4] = __float2half_rn(b.x); h[5] = __float2half_rn(b.y);
        h[6] = __float2half_rn(b.z); h[7] = __float2half_rn(b.w);
        *(uint4*)(out + i) = *(const uint4*)h;
    }
}

// ---------------- prep: all 6 weight transposes in ONE launch -----------------
// (keeps launch count low so ncu -s 5 lands on a GEMM, and cuts prep overhead)
// job table (32x32 tiles, flat blockIdx.x):
//   [0,1024)    W_de1 1024x1024 -> Wt_e1[0]
//   [1024,2048) W_nl1 1024x1024 -> Wt_e1[1M]
//   [2048,4096) W_de2 1024x2048 -> Wt_e2[0]
//   [4096,6144) W_nl2 1024x2048 -> Wt_e2[2M]
//   [6144,8192) W_d1  2048x1024 -> Wt_d1
//   [8192,9216) W_d2  1024x1024 -> Wt_d2
__global__ void transpose_all_kernel(
    const float* __restrict__ W_de1, const float* __restrict__ W_nl1,
    const float* __restrict__ W_de2, const float* __restrict__ W_nl2,
    const float* __restrict__ W_d1,  const float* __restrict__ W_d2,
    __half* __restrict__ Wt_e1, __half* __restrict__ Wt_e2,
    __half* __restrict__ Wt_d1, __half* __restrict__ Wt_d2)
{
    const int bid = blockIdx.x;
    const float* in; __half* out; int K, N, tile;
    if      (bid < 1024) { in = W_de1; out = Wt_e1;                          K = 1024; N = 1024; tile = bid; }
    else if (bid < 2048) { in = W_nl1; out = Wt_e1 + (size_t)HID * D_IN;     K = 1024; N = 1024; tile = bid - 1024; }
    else if (bid < 4096) { in = W_de2; out = Wt_e2;                          K = 1024; N = 2048; tile = bid - 2048; }
    else if (bid < 6144) { in = W_nl2; out = Wt_e2 + (size_t)INTD * HID;     K = 1024; N = 2048; tile = bid - 4096; }
    else if (bid < 8192) { in = W_d1;  out = Wt_d1;                          K = 2048; N = 1024; tile = bid - 6144; }
    else                 { in = W_d2;  out = Wt_d2;                          K = 1024; N = 1024; tile = bid - 8192; }

    __shared__ float t[32][33];
    const int ntx = N / 32;
    const int n0 = (tile % ntx) * 32;
    const int k0 = (tile / ntx) * 32;
    #pragma unroll
    for (int j = threadIdx.y; j < 32; j += 8)
        t[j][threadIdx.x] = in[(size_t)(k0 + j) * N + n0 + threadIdx.x];
    __syncthreads();
    #pragma unroll
    for (int j = threadIdx.y; j < 32; j += 8)
        out[(size_t)(n0 + j) * K + k0 + threadIdx.x] = __float2half_rn(t[threadIdx.x][j]);
}

// ---------------- fp16 tensor-core GEMM --------------------------------------
// C[M,N] = act(A @ Bt^T + bias). A: [M,K] half. Bt: [N,K] half (K-major).
// SMEM: 128B rows, XOR granule swizzle g' = g ^ (row & 7).
// 4-stage cp.async pipeline, issues spread across kh-steps, register
// double-buffered fragments, ONE commit per iteration (exact wait-group math).
template<bool RELU, bool GATHER, bool SCATTER, bool SPLIT, bool OUT_HALF>
__global__ void __launch_bounds__(256, 1)
moe_gemm_h(const __half* __restrict__ A,
           const __half* __restrict__ Bt0, const __half* __restrict__ Bt1,
           const float* __restrict__ bias0, const float* __restrict__ bias1,
           void* __restrict__ Cv, int M, int N, int K)
{
    const int n0 = SPLIT ? g_cnt0 : M;
    const int e  = SPLIT ? (int)blockIdx.z : 0;
    const int lo = (e == 0) ? 0  : n0;
    const int hi = (e == 0) ? n0 : M;
    const int row0 = blockIdx.y * BM;
    if (SPLIT && (row0 >= hi || row0 + BM <= lo)) return;
    const int col0 = blockIdx.x * BN;

    const __half* __restrict__ Bt   = (e == 0) ? Bt0   : Bt1;
    const float*  __restrict__ bias = (e == 0) ? bias0 : bias1;

    extern __shared__ char smem[];
    const uint32_t sbase = smem_u32(smem);

    const int tid   = threadIdx.x;
    const int warp  = tid >> 5;
    const int lane  = tid & 31;
    const int warpM = warp >> 2;      // 0..1 (64 rows)
    const int warpN = warp & 3;       // 0..3 (64 cols)
    const int g  = lane >> 2;         // 0..7
    const int tg = lane & 3;          // 0..3

    // ---- fill addressing (granule = 16B = 8 halfs; 8 granules per row) ----
    const __half* aSrcp[4];
    uint32_t aDstp[4], aSz[4];
    #pragma unroll
    for (int s = 0; s < 4; s++) {
        int idx = tid + s * 256;
        int r = idx >> 3, gr = idx & 7;
        int m = row0 + r;
        bool v = (!SPLIT) || (m >= lo && m < hi);
        aSz[s]   = v ? 16u : 0u;
        aSrcp[s] = A + (size_t)(GATHER ? (v ? g_perm[m] : 0) : m) * K + gr * 8;
        aDstp[s] = sbase + (uint32_t)(r * ROWB + ((gr ^ (r & 7)) * 16));
    }
    const __half* bSrcp[8];
    uint32_t bDstp[8];
    #pragma unroll
    for (int s = 0; s < 8; s++) {
        int idx = tid + s * 256;
        int r = idx >> 3, gr = idx & 7;
        bSrcp[s] = Bt + (size_t)(col0 + r) * K + gr * 8;
        bDstp[s] = sbase + A_ST + (uint32_t)(r * ROWB + ((gr ^ (r & 7)) * 16));
    }

    const int nch = K / BK;

    auto issue_all = [&](int c) {
        const uint32_t so = (uint32_t)((c % STAGES) * STAGE_BYTES);
        const int ko = c * BK;
        #pragma unroll
        for (int s = 0; s < 4; s++)
            CP_ASYNC16(aDstp[s] + so, aSrcp[s] + ko, aSz[s]);
        #pragma unroll
        for (int s = 0; s < 8; s++)
            CP_ASYNC16(bDstp[s] + so, bSrcp[s] + ko, 16u);
        CP_COMMIT();
    };

    #pragma unroll
    for (int c = 0; c < STAGES - 1; c++) issue_all(c);

    float acc[4][8][4];
    #pragma unroll
    for (int mt = 0; mt < 4; mt++)
        #pragma unroll
        for (int nt = 0; nt < 8; nt++)
            #pragma unroll
            for (int i = 0; i < 4; i++) acc[mt][nt][i] = 0.0f;

    // per-warp ldmatrix row bases + swizzle masks
    uint32_t aRowOff[4]; int aRm[4];
    #pragma unroll
    for (int mt = 0; mt < 4; mt++) {
        int rr = warpM * 64 + mt * 16 + (lane & 15);
        aRowOff[mt] = sbase + (uint32_t)(rr * ROWB);
        aRm[mt] = rr & 7;
    }
    const int aChunk = lane >> 4;                 // 0..1
    uint32_t bRowOff[4]; int bRm[4];
    #pragma unroll
    for (int p = 0; p < 4; p++) {
        int rr = warpN * 64 + p * 16 + (lane & 7) + ((lane >> 4) << 3);
        bRowOff[p] = sbase + A_ST + (uint32_t)(rr * ROWB);
        bRm[p] = rr & 7;
    }
    const int bChunk = (lane >> 3) & 1;           // 0..1

    uint32_t af[2][4][4], bf[2][4][4];

    auto load_frags = [&](int buf, uint32_t so, int kh) {
        #pragma unroll
        for (int mt = 0; mt < 4; mt++) {
            uint32_t ad = aRowOff[mt] + so
                + (uint32_t)(((kh * 2 + aChunk) ^ aRm[mt]) * 16);
            LDSM_X4(af[buf][mt][0], af[buf][mt][1], af[buf][mt][2], af[buf][mt][3], ad);
        }
        #pragma unroll
        for (int p = 0; p < 4; p++) {
            uint32_t bd = bRowOff[p] + so
                + (uint32_t)(((kh * 2 + bChunk) ^ bRm[p]) * 16);
            LDSM_X4(bf[buf][p][0], bf[buf][p][1], bf[buf][p][2], bf[buf][p][3], bd);
        }
    };

    for (int i = 0; i < nch; i++) {
        CP_WAIT(STAGES - 2);
        __syncthreads();

        // prefetch chunk pc = i + STAGES-1 into the stage just freed; its 12
        // cp.asyncs are spread across the 4 kh-steps (3 per step), with ONE
        // commit per iteration so CP_WAIT(2) always guarantees stage i done.
        const int pc = i + STAGES - 1;
        const bool pf = (pc < nch);
        const uint32_t pso = (uint32_t)((pc % STAGES) * STAGE_BYTES);
        const int pko = pc * BK;

        const uint32_t so = (uint32_t)((i % STAGES) * STAGE_BYTES);
        load_frags(0, so, 0);
        #pragma unroll
        for (int kh = 0; kh < BK / 16; kh++) {    // 4 k-steps of 16
            const int cur = kh & 1;
            if (kh + 1 < BK / 16) load_frags(cur ^ 1, so, kh + 1);
            if (pf) {
                CP_ASYNC16(aDstp[kh] + pso,         aSrcp[kh] + pko,         aSz[kh]);
                CP_ASYNC16(bDstp[2*kh] + pso,       bSrcp[2*kh] + pko,       16u);
                CP_ASYNC16(bDstp[2*kh + 1] + pso,   bSrcp[2*kh + 1] + pko,   16u);
            }
            if (kh == BK / 16 - 1) CP_COMMIT();   // one group per iteration, always
            #pragma unroll
            for (int mt = 0; mt < 4; mt++)
                #pragma unroll
                for (int nt = 0; nt < 8; nt++)
                    MMA16816(acc[mt][nt], af[cur][mt],
                             bf[cur][nt >> 1][(nt & 1) * 2],
                             bf[cur][nt >> 1][(nt & 1) * 2 + 1]);
        }
    }

    // ---- epilogue ----
    #pragma unroll
    for (int mt = 0; mt < 4; mt++) {
        const int mBase = row0 + warpM * 64 + mt * 16 + g;
        #pragma unroll
        for (int nt = 0; nt < 8; nt++) {
            const int c = col0 + warpN * 64 + nt * 8 + 2 * tg;
            const float bv0 = bias[c];
            const float bv1 = bias[c + 1];
            #pragma unroll
            for (int half_i = 0; half_i < 2; half_i++) {
                const int m = mBase + half_i * 8;
                if (SPLIT && (m < lo || m >= hi)) continue;
                float v0 = acc[mt][nt][half_i * 2 + 0] + bv0;
                float v1 = acc[mt][nt][half_i * 2 + 1] + bv1;
                if (RELU) { v0 = fmaxf(v0, 0.f); v1 = fmaxf(v1, 0.f); }
                const int mo = SCATTER ? g_perm[m] : m;
                if (OUT_HALF) {
                    __half2 hv;
                    hv.x = __float2half_rn(v0);
                    hv.y = __float2half_rn(v1);
                    *(__half2*)((__half*)Cv + (size_t)mo * N + c) = hv;
                } else {
                    *(float2*)((float*)Cv + (size_t)mo * N + c) = make_float2(v0, v1);
                }
            }
        }
    }
}

// ---------------- launch ------------------------------------------------------
extern "C" void kernel_launch(void* const* d_in, const int* in_sizes, int n_in,
                              void* d_out, int out_size)
{
    const float* x     = (const float*)d_in[0];
    const int*   lang  = (const int*)  d_in[1];
    const float* W_de1 = (const float*)d_in[2];
    const float* b_de1 = (const float*)d_in[3];
    const float* W_de2 = (const float*)d_in[4];
    const float* b_de2 = (const float*)d_in[5];
    const float* W_nl1 = (const float*)d_in[6];
    const float* b_nl1 = (const float*)d_in[7];
    const float* W_nl2 = (const float*)d_in[8];
    const float* b_nl2 = (const float*)d_in[9];
    const float* W_d1  = (const float*)d_in[10];
    const float* b_d1  = (const float*)d_in[11];
    const float* W_d2  = (const float*)d_in[12];
    const float* b_d2  = (const float*)d_in[13];
    float* out = (float*)d_out;

    const int M = in_sizes[1];  // 32768

    __half *xh, *h1, *enc, *Wt_e1, *Wt_e2, *Wt_d1, *Wt_d2;
    cudaGetSymbolAddress((void**)&xh,    g_xh);
    cudaGetSymbolAddress((void**)&h1,    g_h1);
    cudaGetSymbolAddress((void**)&enc,   g_enc);
    cudaGetSymbolAddress((void**)&Wt_e1, g_Wt_e1);
    cudaGetSymbolAddress((void**)&Wt_e2, g_Wt_e2);
    cudaGetSymbolAddress((void**)&Wt_d1, g_Wt_d1);
    cudaGetSymbolAddress((void**)&Wt_d2, g_Wt_d2);

    cudaFuncSetAttribute(moe_gemm_h<true,  true,  false, true,  true >,
                         cudaFuncAttributeMaxDynamicSharedMemorySize, SMEM_DYN);
    cudaFuncSetAttribute(moe_gemm_h<false, false, false, true,  true >,
                         cudaFuncAttributeMaxDynamicSharedMemorySize, SMEM_DYN);
    cudaFuncSetAttribute(moe_gemm_h<true,  false, false, false, true >,
                         cudaFuncAttributeMaxDynamicSharedMemorySize, SMEM_DYN);
    cudaFuncSetAttribute(moe_gemm_h<false, false, true,  false, false>,
                         cudaFuncAttributeMaxDynamicSharedMemorySize, SMEM_DYN);

    // launch order matters for ncu -s 5: 0=init, 1=perm, 2=f2h, 3=transpose_all,
    // 4=GEMM L1, 5=GEMM L2 (profiled), 6=L3, 7=L4.
    init_counters_kernel<<<1, 1>>>();
    build_perm_kernel<<<(M + 255) / 256, 256>>>(lang, M);

    {
        int n = M * D_IN;
        f2h_kernel<<<(n / 8 + 255) / 256, 256>>>(x, xh, n);
    }
    transpose_all_kernel<<<9216, dim3(32, 8)>>>(
        W_de1, W_nl1, W_de2, W_nl2, W_d1, W_d2, Wt_e1, Wt_e2, Wt_d1, Wt_d2);

    // L1: h1 = relu(x[perm] @ W1_e + b1_e)   [split, gather]
    moe_gemm_h<true, true, false, true, true>
        <<<dim3(HID / BN, M / BM, 2), 256, SMEM_DYN>>>(
        xh, Wt_e1, Wt_e1 + (size_t)HID * D_IN, b_de1, b_nl1, h1, M, HID, D_IN);

    // L2: enc = h1 @ W2_e + b2_e             [split]
    moe_gemm_h<false, false, false, true, true>
        <<<dim3(INTD / BN, M / BM, 2), 256, SMEM_DYN>>>(
        h1, Wt_e2, Wt_e2 + (size_t)INTD * HID, b_de2, b_nl2, enc, M, INTD, HID);

    // L3: h1 = relu(enc @ W_d1 + b_d1)       [shared decoder]
    moe_gemm_h<true, false, false, false, true>
        <<<dim3(HID / BN, M / BM, 1), 256, SMEM_DYN>>>(
        enc, Wt_d1, Wt_d1, b_d1, b_d1, h1, M, HID, INTD);

    // L4: out[perm] = h1 @ W_d2 + b_d2       [scatter, f32 out]
    moe_gemm_h<false, false, true, false, false>
        <<<dim3(D_IN / BN, M / BM, 1), 256, SMEM_DYN>>>(
        h1, Wt_d2, Wt_d2, b_d2, b_d2, out, M, D_IN, HID);
}

// round 12
// speedup vs baseline: 3.0077x; 1.0086x over previous
#include <cuda_runtime.h>
#include <cuda_fp16.h>
#include <cstdint>
#include <cstddef>

// Problem shapes (fixed)
#define NROWS 32768
#define D_IN  1024
#define HID   1024
#define INTD  2048

// GEMM tiling: 128x256 CTA tile, 64x64 warp tile, K-chunk 64 halfs (128B rows)
#define BM 128
#define BN 256
#define BK 64
#define STAGES 4
#define ROWB 128                            // 64 halfs, no pad (XOR swizzle)
#define A_ST (BM * ROWB)                    // 16384
#define B_ST (BN * ROWB)                    // 32768
#define STAGE_BYTES (A_ST + B_ST)           // 49152
#define SMEM_DYN (STAGES * STAGE_BYTES)     // 196608

// ---------------- scratch (device globals: allocation-free rule) ------------
__device__ int    g_cnt0, g_cnt1;
__device__ int    g_perm[NROWS];
__device__ __half g_xh [(size_t)NROWS * D_IN];
__device__ __half g_h1 [(size_t)NROWS * HID];
__device__ __half g_enc[(size_t)NROWS * INTD];
// Pre-transposed half weights: [n][k] K-major
__device__ __half g_Wt_e1[(size_t)2 * HID  * D_IN];
__device__ __half g_Wt_e2[(size_t)2 * INTD * HID ];
__device__ __half g_Wt_d1[(size_t)HID  * INTD];
__device__ __half g_Wt_d2[(size_t)D_IN * HID ];

// ---------------- helpers ----------------------------------------------------
__device__ __forceinline__ uint32_t smem_u32(const void* p) {
    uint32_t a;
    asm("{ .reg .u64 t; cvta.to.shared.u64 t, %1; cvt.u32.u64 %0, t; }" : "=r"(a) : "l"(p));
    return a;
}

#define CP_ASYNC16(dst, src, sz) \
    asm volatile("cp.async.cg.shared.global [%0], [%1], 16, %2;" \
                 :: "r"(dst), "l"(src), "r"(sz) : "memory")
#define CP_COMMIT() asm volatile("cp.async.commit_group;" ::: "memory")
#define CP_WAIT(n)  asm volatile("cp.async.wait_group %0;" :: "n"(n) : "memory")

#define LDSM_X4(r0, r1, r2, r3, addr) \
    asm volatile("ldmatrix.sync.aligned.m8n8.x4.shared.b16 {%0,%1,%2,%3}, [%4];" \
                 : "=r"(r0), "=r"(r1), "=r"(r2), "=r"(r3) : "r"(addr))

#define MMA16816(d, a, b0, b1) \
    asm volatile("mma.sync.aligned.m16n8k16.row.col.f32.f16.f16.f32 " \
                 "{%0,%1,%2,%3}, {%4,%5,%6,%7}, {%8,%9}, {%0,%1,%2,%3};" \
                 : "+f"((d)[0]), "+f"((d)[1]), "+f"((d)[2]), "+f"((d)[3]) \
                 : "r"((a)[0]), "r"((a)[1]), "r"((a)[2]), "r"((a)[3]), \
                   "r"(b0), "r"(b1))

// ---------------- routing ----------------------------------------------------
__global__ void build_perm_kernel(const int* __restrict__ lang, int n) {
    int i = blockIdx.x * blockDim.x + threadIdx.x;
    if (i < n) {
        if (lang[i] == 0) g_perm[atomicAdd(&g_cnt0, 1)] = i;
        else              g_perm[n - 1 - atomicAdd(&g_cnt1, 1)] = i;
    }
}

// ---------------- prep: ONE kernel for counters + f2h(x) + all transposes ----
// blocks [0, 9216):     32x32 transpose tiles over the 6 weight matrices
// blocks [9216, 25600): f2h of x (8 elems/thread)
// block 0 thread 0 also zeroes the routing counters (prep runs before perm).
#define TR_BLOCKS 9216
#define F2H_BLOCKS 16384            // 32768*1024 / 8 / 256
__global__ void prep_all_kernel(
    const float* __restrict__ x, __half* __restrict__ xh,
    const float* __restrict__ W_de1, const float* __restrict__ W_nl1,
    const float* __restrict__ W_de2, const float* __restrict__ W_nl2,
    const float* __restrict__ W_d1,  const float* __restrict__ W_d2,
    __half* __restrict__ Wt_e1, __half* __restrict__ Wt_e2,
    __half* __restrict__ Wt_d1, __half* __restrict__ Wt_d2)
{
    const int bid = blockIdx.x;
    const int tid = threadIdx.x;
    if (bid == 0 && tid == 0) { g_cnt0 = 0; g_cnt1 = 0; }

    if (bid >= TR_BLOCKS) {
        // ---- f2h of x ----
        int i = ((bid - TR_BLOCKS) * 256 + tid) * 8;
        float4 a = *(const float4*)(x + i);
        float4 b = *(const float4*)(x + i + 4);
        __half h[8];
        h[0] = __float2half_rn(a.x); h[1] = __float2half_rn(a.y);
        h[2] = __float2half_rn(a.z); h[3] = __float2half_rn(a.w);
        h[4] = __float2half_rn(b.x); h[5] = __float2half_rn(b.y);
        h[6] = __float2half_rn(b.z); h[7] = __float2half_rn(b.w);
        *(uint4*)(xh + i) = *(const uint4*)h;
        return;
    }

    // ---- weight transpose: in[K,N] f32 -> out[N,K] half, 32x32 tiles ----
    const float* in; __half* out; int K, N, tile;
    if      (bid < 1024) { in = W_de1; out = Wt_e1;                      K = 1024; N = 1024; tile = bid; }
    else if (bid < 2048) { in = W_nl1; out = Wt_e1 + (size_t)HID * D_IN; K = 1024; N = 1024; tile = bid - 1024; }
    else if (bid < 4096) { in = W_de2; out = Wt_e2;                      K = 1024; N = 2048; tile = bid - 2048; }
    else if (bid < 6144) { in = W_nl2; out = Wt_e2 + (size_t)INTD * HID; K = 1024; N = 2048; tile = bid - 4096; }
    else if (bid < 8192) { in = W_d1;  out = Wt_d1;                      K = 2048; N = 1024; tile = bid - 6144; }
    else                 { in = W_d2;  out = Wt_d2;                      K = 1024; N = 1024; tile = bid - 8192; }

    __shared__ float t[32][33];
    const int tx = tid & 31;
    const int ty = tid >> 5;
    const int ntx = N / 32;
    const int n0 = (tile % ntx) * 32;
    const int k0 = (tile / ntx) * 32;
    #pragma unroll
    for (int j = ty; j < 32; j += 8)
        t[j][tx] = in[(size_t)(k0 + j) * N + n0 + tx];
    __syncthreads();
    #pragma unroll
    for (int j = ty; j < 32; j += 8)
        out[(size_t)(n0 + j) * K + k0 + tx] = __float2half_rn(t[tx][j]);
}

// ---------------- fp16 tensor-core GEMM --------------------------------------
// C[M,N] = act(A @ Bt^T + bias). A: [M,K] half. Bt: [N,K] half (K-major).
// SMEM: 128B rows, XOR granule swizzle g' = g ^ (row & 7).
// 4-stage cp.async pipeline, issues spread across kh-steps, register
// double-buffered fragments, ONE commit per iteration (exact wait-group math).
template<bool RELU, bool GATHER, bool SCATTER, bool SPLIT, bool OUT_HALF>
__global__ void __launch_bounds__(256, 1)
moe_gemm_h(const __half* __restrict__ A,
           const __half* __restrict__ Bt0, const __half* __restrict__ Bt1,
           const float* __restrict__ bias0, const float* __restrict__ bias1,
           void* __restrict__ Cv, int M, int N, int K)
{
    const int n0 = SPLIT ? g_cnt0 : M;
    const int e  = SPLIT ? (int)blockIdx.z : 0;
    const int lo = (e == 0) ? 0  : n0;
    const int hi = (e == 0) ? n0 : M;
    const int row0 = blockIdx.y * BM;
    if (SPLIT && (row0 >= hi || row0 + BM <= lo)) return;
    const int col0 = blockIdx.x * BN;

    const __half* __restrict__ Bt   = (e == 0) ? Bt0   : Bt1;
    const float*  __restrict__ bias = (e == 0) ? bias0 : bias1;

    extern __shared__ char smem[];
    const uint32_t sbase = smem_u32(smem);

    const int tid   = threadIdx.x;
    const int warp  = tid >> 5;
    const int lane  = tid & 31;
    const int warpM = warp >> 2;      // 0..1 (64 rows)
    const int warpN = warp & 3;       // 0..3 (64 cols)
    const int g  = lane >> 2;         // 0..7
    const int tg = lane & 3;          // 0..3

    // ---- fill addressing (granule = 16B = 8 halfs; 8 granules per row) ----
    const __half* aSrcp[4];
    uint32_t aDstp[4], aSz[4];
    #pragma unroll
    for (int s = 0; s < 4; s++) {
        int idx = tid + s * 256;
        int r = idx >> 3, gr = idx & 7;
        int m = row0 + r;
        bool v = (!SPLIT) || (m >= lo && m < hi);
        aSz[s]   = v ? 16u : 0u;
        aSrcp[s] = A + (size_t)(GATHER ? (v ? g_perm[m] : 0) : m) * K + gr * 8;
        aDstp[s] = sbase + (uint32_t)(r * ROWB + ((gr ^ (r & 7)) * 16));
    }
    const __half* bSrcp[8];
    uint32_t bDstp[8];
    #pragma unroll
    for (int s = 0; s < 8; s++) {
        int idx = tid + s * 256;
        int r = idx >> 3, gr = idx & 7;
        bSrcp[s] = Bt + (size_t)(col0 + r) * K + gr * 8;
        bDstp[s] = sbase + A_ST + (uint32_t)(r * ROWB + ((gr ^ (r & 7)) * 16));
    }

    const int nch = K / BK;

    auto issue_all = [&](int c) {
        const uint32_t so = (uint32_t)((c % STAGES) * STAGE_BYTES);
        const int ko = c * BK;
        #pragma unroll
        for (int s = 0; s < 4; s++)
            CP_ASYNC16(aDstp[s] + so, aSrcp[s] + ko, aSz[s]);
        #pragma unroll
        for (int s = 0; s < 8; s++)
            CP_ASYNC16(bDstp[s] + so, bSrcp[s] + ko, 16u);
        CP_COMMIT();
    };

    #pragma unroll
    for (int c = 0; c < STAGES - 1; c++) issue_all(c);

    float acc[4][8][4];
    #pragma unroll
    for (int mt = 0; mt < 4; mt++)
        #pragma unroll
        for (int nt = 0; nt < 8; nt++)
            #pragma unroll
            for (int i = 0; i < 4; i++) acc[mt][nt][i] = 0.0f;

    // per-warp ldmatrix row bases + swizzle masks
    uint32_t aRowOff[4]; int aRm[4];
    #pragma unroll
    for (int mt = 0; mt < 4; mt++) {
        int rr = warpM * 64 + mt * 16 + (lane & 15);
        aRowOff[mt] = sbase + (uint32_t)(rr * ROWB);
        aRm[mt] = rr & 7;
    }
    const int aChunk = lane >> 4;                 // 0..1
    uint32_t bRowOff[4]; int bRm[4];
    #pragma unroll
    for (int p = 0; p < 4; p++) {
        int rr = warpN * 64 + p * 16 + (lane & 7) + ((lane >> 4) << 3);
        bRowOff[p] = sbase + A_ST + (uint32_t)(rr * ROWB);
        bRm[p] = rr & 7;
    }
    const int bChunk = (lane >> 3) & 1;           // 0..1

    uint32_t af[2][4][4], bf[2][4][4];

    auto load_frags = [&](int buf, uint32_t so, int kh) {
        #pragma unroll
        for (int mt = 0; mt < 4; mt++) {
            uint32_t ad = aRowOff[mt] + so
                + (uint32_t)(((kh * 2 + aChunk) ^ aRm[mt]) * 16);
            LDSM_X4(af[buf][mt][0], af[buf][mt][1], af[buf][mt][2], af[buf][mt][3], ad);
        }
        #pragma unroll
        for (int p = 0; p < 4; p++) {
            uint32_t bd = bRowOff[p] + so
                + (uint32_t)(((kh * 2 + bChunk) ^ bRm[p]) * 16);
            LDSM_X4(bf[buf][p][0], bf[buf][p][1], bf[buf][p][2], bf[buf][p][3], bd);
        }
    };

    for (int i = 0; i < nch; i++) {
        CP_WAIT(STAGES - 2);
        __syncthreads();

        // prefetch chunk pc = i + STAGES-1 into the stage just freed; its 12
        // cp.asyncs are spread across the 4 kh-steps (3 per step), with ONE
        // commit per iteration so CP_WAIT(2) always guarantees stage i done.
        const int pc = i + STAGES - 1;
        const bool pf = (pc < nch);
        const uint32_t pso = (uint32_t)((pc % STAGES) * STAGE_BYTES);
        const int pko = pc * BK;

        const uint32_t so = (uint32_t)((i % STAGES) * STAGE_BYTES);
        load_frags(0, so, 0);
        #pragma unroll
        for (int kh = 0; kh < BK / 16; kh++) {    // 4 k-steps of 16
            const int cur = kh & 1;
            if (kh + 1 < BK / 16) load_frags(cur ^ 1, so, kh + 1);
            if (pf) {
                CP_ASYNC16(aDstp[kh] + pso,         aSrcp[kh] + pko,         aSz[kh]);
                CP_ASYNC16(bDstp[2*kh] + pso,       bSrcp[2*kh] + pko,       16u);
                CP_ASYNC16(bDstp[2*kh + 1] + pso,   bSrcp[2*kh + 1] + pko,   16u);
            }
            if (kh == BK / 16 - 1) CP_COMMIT();   // one group per iteration, always
            #pragma unroll
            for (int mt = 0; mt < 4; mt++)
                #pragma unroll
                for (int nt = 0; nt < 8; nt++)
                    MMA16816(acc[mt][nt], af[cur][mt],
                             bf[cur][nt >> 1][(nt & 1) * 2],
                             bf[cur][nt >> 1][(nt & 1) * 2 + 1]);
        }
    }

    // ---- epilogue ----
    #pragma unroll
    for (int mt = 0; mt < 4; mt++) {
        const int mBase = row0 + warpM * 64 + mt * 16 + g;
        #pragma unroll
        for (int nt = 0; nt < 8; nt++) {
            const int c = col0 + warpN * 64 + nt * 8 + 2 * tg;
            const float bv0 = bias[c];
            const float bv1 = bias[c + 1];
            #pragma unroll
            for (int half_i = 0; half_i < 2; half_i++) {
                const int m = mBase + half_i * 8;
                if (SPLIT && (m < lo || m >= hi)) continue;
                float v0 = acc[mt][nt][half_i * 2 + 0] + bv0;
                float v1 = acc[mt][nt][half_i * 2 + 1] + bv1;
                if (RELU) { v0 = fmaxf(v0, 0.f); v1 = fmaxf(v1, 0.f); }
                const int mo = SCATTER ? g_perm[m] : m;
                if (OUT_HALF) {
                    __half2 hv;
                    hv.x = __float2half_rn(v0);
                    hv.y = __float2half_rn(v1);
                    *(__half2*)((__half*)Cv + (size_t)mo * N + c) = hv;
                } else {
                    *(float2*)((float*)Cv + (size_t)mo * N + c) = make_float2(v0, v1);
                }
            }
        }
    }
}

// ---------------- launch ------------------------------------------------------
extern "C" void kernel_launch(void* const* d_in, const int* in_sizes, int n_in,
                              void* d_out, int out_size)
{
    const float* x     = (const float*)d_in[0];
    const int*   lang  = (const int*)  d_in[1];
    const float* W_de1 = (const float*)d_in[2];
    const float* b_de1 = (const float*)d_in[3];
    const float* W_de2 = (const float*)d_in[4];
    const float* b_de2 = (const float*)d_in[5];
    const float* W_nl1 = (const float*)d_in[6];
    const float* b_nl1 = (const float*)d_in[7];
    const float* W_nl2 = (const float*)d_in[8];
    const float* b_nl2 = (const float*)d_in[9];
    const float* W_d1  = (const float*)d_in[10];
    const float* b_d1  = (const float*)d_in[11];
    const float* W_d2  = (const float*)d_in[12];
    const float* b_d2  = (const float*)d_in[13];
    float* out = (float*)d_out;

    const int M = in_sizes[1];  // 32768

    __half *xh, *h1, *enc, *Wt_e1, *Wt_e2, *Wt_d1, *Wt_d2;
    cudaGetSymbolAddress((void**)&xh,    g_xh);
    cudaGetSymbolAddress((void**)&h1,    g_h1);
    cudaGetSymbolAddress((void**)&enc,   g_enc);
    cudaGetSymbolAddress((void**)&Wt_e1, g_Wt_e1);
    cudaGetSymbolAddress((void**)&Wt_e2, g_Wt_e2);
    cudaGetSymbolAddress((void**)&Wt_d1, g_Wt_d1);
    cudaGetSymbolAddress((void**)&Wt_d2, g_Wt_d2);

    cudaFuncSetAttribute(moe_gemm_h<true,  true,  false, true,  true >,
                         cudaFuncAttributeMaxDynamicSharedMemorySize, SMEM_DYN);
    cudaFuncSetAttribute(moe_gemm_h<false, false, false, true,  true >,
                         cudaFuncAttributeMaxDynamicSharedMemorySize, SMEM_DYN);
    cudaFuncSetAttribute(moe_gemm_h<true,  false, false, false, true >,
                         cudaFuncAttributeMaxDynamicSharedMemorySize, SMEM_DYN);
    cudaFuncSetAttribute(moe_gemm_h<false, false, true,  false, false>,
                         cudaFuncAttributeMaxDynamicSharedMemorySize, SMEM_DYN);

    // Launch order (profiler captures our launch index 3):
    //   0 = prep_all (counters + f2h + transposes)
    //   1 = build_perm
    //   2 = GEMM L1
    //   3 = GEMM L2   <-- ncu lands here
    //   4 = GEMM L3, 5 = GEMM L4
    prep_all_kernel<<<TR_BLOCKS + F2H_BLOCKS, 256>>>(
        x, xh, W_de1, W_nl1, W_de2, W_nl2, W_d1, W_d2,
        Wt_e1, Wt_e2, Wt_d1, Wt_d2);
    build_perm_kernel<<<(M + 255) / 256, 256>>>(lang, M);

    // L1: h1 = relu(x[perm] @ W1_e + b1_e)   [split, gather]
    moe_gemm_h<true, true, false, true, true>
        <<<dim3(HID / BN, M / BM, 2), 256, SMEM_DYN>>>(
        xh, Wt_e1, Wt_e1 + (size_t)HID * D_IN, b_de1, b_nl1, h1, M, HID, D_IN);

    // L2: enc = h1 @ W2_e + b2_e             [split]
    moe_gemm_h<false, false, false, true, true>
        <<<dim3(INTD / BN, M / BM, 2), 256, SMEM_DYN>>>(
        h1, Wt_e2, Wt_e2 + (size_t)INTD * HID, b_de2, b_nl2, enc, M, INTD, HID);

    // L3: h1 = relu(enc @ W_d1 + b_d1)       [shared decoder]
    moe_gemm_h<true, false, false, false, true>
        <<<dim3(HID / BN, M / BM, 1), 256, SMEM_DYN>>>(
        enc, Wt_d1, Wt_d1, b_d1, b_d1, h1, M, HID, INTD);

    // L4: out[perm] = h1 @ W_d2 + b_d2       [scatter, f32 out]
    moe_gemm_h<false, false, true, false, false>
        <<<dim3(D_IN / BN, M / BM, 1), 256, SMEM_DYN>>>(
        h1, Wt_d2, Wt_d2, b_d2, b_d2, out, M, D_IN, HID);
}

// round 13
// speedup vs baseline: 3.1537x; 1.0486x over previous
#include <cuda_runtime.h>
#include <cuda_fp16.h>
#include <cstdint>
#include <cstddef>

// Problem shapes (fixed)
#define NROWS 32768
#define D_IN  1024
#define HID   1024
#define INTD  2048

// GEMM tiling: 64x256 CTA tile, 64x64 warp tile (4 warps), K-chunk 64 halfs.
// 2 CTAs/SM so barrier stalls of one CTA overlap with the other's MMAs.
#define BM 64
#define BN 256
#define BK 64
#define STAGES 2
#define ROWB 128                            // 64 halfs, no pad (XOR swizzle)
#define A_ST (BM * ROWB)                    // 8192
#define B_ST (BN * ROWB)                    // 32768
#define STAGE_BYTES (A_ST + B_ST)           // 40960
#define SMEM_DYN (STAGES * STAGE_BYTES)     // 81920 (x2 CTAs = 160KB/SM)
#define NTHR 128

// ---------------- scratch (device globals: allocation-free rule) ------------
__device__ int    g_cnt0, g_cnt1;
__device__ int    g_perm[NROWS];
__device__ __half g_xh [(size_t)NROWS * D_IN];
__device__ __half g_h1 [(size_t)NROWS * HID];
__device__ __half g_enc[(size_t)NROWS * INTD];
// Pre-transposed half weights: [n][k] K-major
__device__ __half g_Wt_e1[(size_t)2 * HID  * D_IN];
__device__ __half g_Wt_e2[(size_t)2 * INTD * HID ];
__device__ __half g_Wt_d1[(size_t)HID  * INTD];
__device__ __half g_Wt_d2[(size_t)D_IN * HID ];

// ---------------- helpers ----------------------------------------------------
__device__ __forceinline__ uint32_t smem_u32(const void* p) {
    uint32_t a;
    asm("{ .reg .u64 t; cvta.to.shared.u64 t, %1; cvt.u32.u64 %0, t; }" : "=r"(a) : "l"(p));
    return a;
}

#define CP_ASYNC16(dst, src, sz) \
    asm volatile("cp.async.cg.shared.global [%0], [%1], 16, %2;" \
                 :: "r"(dst), "l"(src), "r"(sz) : "memory")
#define CP_COMMIT() asm volatile("cp.async.commit_group;" ::: "memory")
#define CP_WAIT(n)  asm volatile("cp.async.wait_group %0;" :: "n"(n) : "memory")

#define LDSM_X4(r0, r1, r2, r3, addr) \
    asm volatile("ldmatrix.sync.aligned.m8n8.x4.shared.b16 {%0,%1,%2,%3}, [%4];" \
                 : "=r"(r0), "=r"(r1), "=r"(r2), "=r"(r3) : "r"(addr))

#define MMA16816(d, a, b0, b1) \
    asm volatile("mma.sync.aligned.m16n8k16.row.col.f32.f16.f16.f32 " \
                 "{%0,%1,%2,%3}, {%4,%5,%6,%7}, {%8,%9}, {%0,%1,%2,%3};" \
                 : "+f"((d)[0]), "+f"((d)[1]), "+f"((d)[2]), "+f"((d)[3]) \
                 : "r"((a)[0]), "r"((a)[1]), "r"((a)[2]), "r"((a)[3]), \
                   "r"(b0), "r"(b1))

// ---------------- routing ----------------------------------------------------
__global__ void build_perm_kernel(const int* __restrict__ lang, int n) {
    int i = blockIdx.x * blockDim.x + threadIdx.x;
    if (i < n) {
        if (lang[i] == 0) g_perm[atomicAdd(&g_cnt0, 1)] = i;
        else              g_perm[n - 1 - atomicAdd(&g_cnt1, 1)] = i;
    }
}

// ---------------- prep: ONE kernel for counters + f2h(x) + all transposes ----
#define TR_BLOCKS 9216
#define F2H_BLOCKS 16384            // 32768*1024 / 8 / 256
__global__ void prep_all_kernel(
    const float* __restrict__ x, __half* __restrict__ xh,
    const float* __restrict__ W_de1, const float* __restrict__ W_nl1,
    const float* __restrict__ W_de2, const float* __restrict__ W_nl2,
    const float* __restrict__ W_d1,  const float* __restrict__ W_d2,
    __half* __restrict__ Wt_e1, __half* __restrict__ Wt_e2,
    __half* __restrict__ Wt_d1, __half* __restrict__ Wt_d2)
{
    const int bid = blockIdx.x;
    const int tid = threadIdx.x;
    if (bid == 0 && tid == 0) { g_cnt0 = 0; g_cnt1 = 0; }

    if (bid >= TR_BLOCKS) {
        int i = ((bid - TR_BLOCKS) * 256 + tid) * 8;
        float4 a = *(const float4*)(x + i);
        float4 b = *(const float4*)(x + i + 4);
        __half h[8];
        h[0] = __float2half_rn(a.x); h[1] = __float2half_rn(a.y);
        h[2] = __float2half_rn(a.z); h[3] = __float2half_rn(a.w);
        h[4] = __float2half_rn(b.x); h[5] = __float2half_rn(b.y);
        h[6] = __float2half_rn(b.z); h[7] = __float2half_rn(b.w);
        *(uint4*)(xh + i) = *(const uint4*)h;
        return;
    }

    const float* in; __half* out; int K, N, tile;
    if      (bid < 1024) { in = W_de1; out = Wt_e1;                      K = 1024; N = 1024; tile = bid; }
    else if (bid < 2048) { in = W_nl1; out = Wt_e1 + (size_t)HID * D_IN; K = 1024; N = 1024; tile = bid - 1024; }
    else if (bid < 4096) { in = W_de2; out = Wt_e2;                      K = 1024; N = 2048; tile = bid - 2048; }
    else if (bid < 6144) { in = W_nl2; out = Wt_e2 + (size_t)INTD * HID; K = 1024; N = 2048; tile = bid - 4096; }
    else if (bid < 8192) { in = W_d1;  out = Wt_d1;                      K = 2048; N = 1024; tile = bid - 6144; }
    else                 { in = W_d2;  out = Wt_d2;                      K = 1024; N = 1024; tile = bid - 8192; }

    __shared__ float t[32][33];
    const int tx = tid & 31;
    const int ty = tid >> 5;
    const int ntx = N / 32;
    const int n0 = (tile % ntx) * 32;
    const int k0 = (tile / ntx) * 32;
    #pragma unroll
    for (int j = ty; j < 32; j += 8)
        t[j][tx] = in[(size_t)(k0 + j) * N + n0 + tx];
    __syncthreads();
    #pragma unroll
    for (int j = ty; j < 32; j += 8)
        out[(size_t)(n0 + j) * K + k0 + tx] = __float2half_rn(t[tx][j]);
}

// ---------------- fp16 tensor-core GEMM --------------------------------------
// C[M,N] = act(A @ Bt^T + bias). A: [M,K] half. Bt: [N,K] half (K-major).
// 64x256 CTA tile, 4 warps (each 64x64), 2-stage cp.async pipeline:
//   iter i: CP_WAIT(1) [chunk i ready]; bar; compute(i); bar; issue(i+2)
// Two CTAs per SM run these pipelines out of phase, covering each other's
// barrier/wait windows on the shared tensor pipes.
template<bool RELU, bool GATHER, bool SCATTER, bool SPLIT, bool OUT_HALF>
__global__ void __launch_bounds__(NTHR, 2)
moe_gemm_h(const __half* __restrict__ A,
           const __half* __restrict__ Bt0, const __half* __restrict__ Bt1,
           const float* __restrict__ bias0, const float* __restrict__ bias1,
           void* __restrict__ Cv, int M, int N, int K)
{
    const int n0 = SPLIT ? g_cnt0 : M;
    const int e  = SPLIT ? (int)blockIdx.z : 0;
    const int lo = (e == 0) ? 0  : n0;
    const int hi = (e == 0) ? n0 : M;
    const int row0 = blockIdx.y * BM;
    if (SPLIT && (row0 >= hi || row0 + BM <= lo)) return;
    const int col0 = blockIdx.x * BN;

    const __half* __restrict__ Bt   = (e == 0) ? Bt0   : Bt1;
    const float*  __restrict__ bias = (e == 0) ? bias0 : bias1;

    extern __shared__ char smem[];
    const uint32_t sbase = smem_u32(smem);

    const int tid  = threadIdx.x;
    const int warp = tid >> 5;        // 0..3 = warpN (64 cols each)
    const int lane = tid & 31;
    const int g  = lane >> 2;         // 0..7
    const int tg = lane & 3;          // 0..3

    // ---- fill addressing (granule = 16B = 8 halfs; 8 granules per row) ----
    // A: 64 rows x 8 gr = 512 slots -> 4/thread. B: 256 x 8 = 2048 -> 16/thread.
    const __half* aSrcp[4];
    uint32_t aDstp[4], aSz[4];
    #pragma unroll
    for (int s = 0; s < 4; s++) {
        int idx = tid + s * NTHR;
        int r = idx >> 3, gr = idx & 7;
        int m = row0 + r;
        bool v = (!SPLIT) || (m >= lo && m < hi);
        aSz[s]   = v ? 16u : 0u;
        aSrcp[s] = A + (size_t)(GATHER ? (v ? g_perm[m] : 0) : m) * K + gr * 8;
        aDstp[s] = sbase + (uint32_t)(r * ROWB + ((gr ^ (r & 7)) * 16));
    }
    const __half* bSrcp[16];
    uint32_t bDstp[16];
    #pragma unroll
    for (int s = 0; s < 16; s++) {
        int idx = tid + s * NTHR;
        int r = idx >> 3, gr = idx & 7;
        bSrcp[s] = Bt + (size_t)(col0 + r) * K + gr * 8;
        bDstp[s] = sbase + A_ST + (uint32_t)(r * ROWB + ((gr ^ (r & 7)) * 16));
    }

    const int nch = K / BK;

    auto issue_all = [&](int c) {
        const uint32_t so = (uint32_t)((c & 1) * STAGE_BYTES);
        const int ko = c * BK;
        #pragma unroll
        for (int s = 0; s < 4; s++)
            CP_ASYNC16(aDstp[s] + so, aSrcp[s] + ko, aSz[s]);
        #pragma unroll
        for (int s = 0; s < 16; s++)
            CP_ASYNC16(bDstp[s] + so, bSrcp[s] + ko, 16u);
        CP_COMMIT();
    };

    issue_all(0);
    issue_all(1);

    float acc[4][8][4];
    #pragma unroll
    for (int mt = 0; mt < 4; mt++)
        #pragma unroll
        for (int nt = 0; nt < 8; nt++)
            #pragma unroll
            for (int i = 0; i < 4; i++) acc[mt][nt][i] = 0.0f;

    // per-warp ldmatrix row bases + swizzle masks
    uint32_t aRowOff[4]; int aRm[4];
    #pragma unroll
    for (int mt = 0; mt < 4; mt++) {
        int rr = mt * 16 + (lane & 15);
        aRowOff[mt] = sbase + (uint32_t)(rr * ROWB);
        aRm[mt] = rr & 7;
    }
    const int aChunk = lane >> 4;                 // 0..1
    uint32_t bRowOff[4]; int bRm[4];
    #pragma unroll
    for (int p = 0; p < 4; p++) {
        int rr = warp * 64 + p * 16 + (lane & 7) + ((lane >> 4) << 3);
        bRowOff[p] = sbase + A_ST + (uint32_t)(rr * ROWB);
        bRm[p] = rr & 7;
    }
    const int bChunk = (lane >> 3) & 1;           // 0..1

    uint32_t af[2][4][4], bf[2][4][4];

    auto load_frags = [&](int buf, uint32_t so, int kh) {
        #pragma unroll
        for (int mt = 0; mt < 4; mt++) {
            uint32_t ad = aRowOff[mt] + so
                + (uint32_t)(((kh * 2 + aChunk) ^ aRm[mt]) * 16);
            LDSM_X4(af[buf][mt][0], af[buf][mt][1], af[buf][mt][2], af[buf][mt][3], ad);
        }
        #pragma unroll
        for (int p = 0; p < 4; p++) {
            uint32_t bd = bRowOff[p] + so
                + (uint32_t)(((kh * 2 + bChunk) ^ bRm[p]) * 16);
            LDSM_X4(bf[buf][p][0], bf[buf][p][1], bf[buf][p][2], bf[buf][p][3], bd);
        }
    };

    for (int i = 0; i < nch; i++) {
        CP_WAIT(1);               // groups outstanding: i, i+1 -> chunk i done
        __syncthreads();

        const uint32_t so = (uint32_t)((i & 1) * STAGE_BYTES);
        load_frags(0, so, 0);
        #pragma unroll
        for (int kh = 0; kh < BK / 16; kh++) {    // 4 k-steps of 16
            const int cur = kh & 1;
            if (kh + 1 < BK / 16) load_frags(cur ^ 1, so, kh + 1);
            #pragma unroll
            for (int mt = 0; mt < 4; mt++)
                #pragma unroll
                for (int nt = 0; nt < 8; nt++)
                    MMA16816(acc[mt][nt], af[cur][mt],
                             bf[cur][nt >> 1][(nt & 1) * 2],
                             bf[cur][nt >> 1][(nt & 1) * 2 + 1]);
        }

        __syncthreads();          // all warps done reading stage i&1
        if (i + 2 < nch) issue_all(i + 2);   // refill the stage just consumed
        else             CP_COMMIT();        // empty group keeps wait math exact
    }

    // ---- epilogue ----
    #pragma unroll
    for (int mt = 0; mt < 4; mt++) {
        const int mBase = row0 + mt * 16 + g;
        #pragma unroll
        for (int nt = 0; nt < 8; nt++) {
            const int c = col0 + warp * 64 + nt * 8 + 2 * tg;
            const float bv0 = bias[c];
            const float bv1 = bias[c + 1];
            #pragma unroll
            for (int half_i = 0; half_i < 2; half_i++) {
                const int m = mBase + half_i * 8;
                if (SPLIT && (m < lo || m >= hi)) continue;
                float v0 = acc[mt][nt][half_i * 2 + 0] + bv0;
                float v1 = acc[mt][nt][half_i * 2 + 1] + bv1;
                if (RELU) { v0 = fmaxf(v0, 0.f); v1 = fmaxf(v1, 0.f); }
                const int mo = SCATTER ? g_perm[m] : m;
                if (OUT_HALF) {
                    __half2 hv;
                    hv.x = __float2half_rn(v0);
                    hv.y = __float2half_rn(v1);
                    *(__half2*)((__half*)Cv + (size_t)mo * N + c) = hv;
                } else {
                    *(float2*)((float*)Cv + (size_t)mo * N + c) = make_float2(v0, v1);
                }
            }
        }
    }
}

// ---------------- launch ------------------------------------------------------
extern "C" void kernel_launch(void* const* d_in, const int* in_sizes, int n_in,
                              void* d_out, int out_size)
{
    const float* x     = (const float*)d_in[0];
    const int*   lang  = (const int*)  d_in[1];
    const float* W_de1 = (const float*)d_in[2];
    const float* b_de1 = (const float*)d_in[3];
    const float* W_de2 = (const float*)d_in[4];
    const float* b_de2 = (const float*)d_in[5];
    const float* W_nl1 = (const float*)d_in[6];
    const float* b_nl1 = (const float*)d_in[7];
    const float* W_nl2 = (const float*)d_in[8];
    const float* b_nl2 = (const float*)d_in[9];
    const float* W_d1  = (const float*)d_in[10];
    const float* b_d1  = (const float*)d_in[11];
    const float* W_d2  = (const float*)d_in[12];
    const float* b_d2  = (const float*)d_in[13];
    float* out = (float*)d_out;

    const int M = in_sizes[1];  // 32768

    __half *xh, *h1, *enc, *Wt_e1, *Wt_e2, *Wt_d1, *Wt_d2;
    cudaGetSymbolAddress((void**)&xh,    g_xh);
    cudaGetSymbolAddress((void**)&h1,    g_h1);
    cudaGetSymbolAddress((void**)&enc,   g_enc);
    cudaGetSymbolAddress((void**)&Wt_e1, g_Wt_e1);
    cudaGetSymbolAddress((void**)&Wt_e2, g_Wt_e2);
    cudaGetSymbolAddress((void**)&Wt_d1, g_Wt_d1);
    cudaGetSymbolAddress((void**)&Wt_d2, g_Wt_d2);

    cudaFuncSetAttribute(moe_gemm_h<true,  true,  false, true,  true >,
                         cudaFuncAttributeMaxDynamicSharedMemorySize, SMEM_DYN);
    cudaFuncSetAttribute(moe_gemm_h<false, false, false, true,  true >,
                         cudaFuncAttributeMaxDynamicSharedMemorySize, SMEM_DYN);
    cudaFuncSetAttribute(moe_gemm_h<true,  false, false, false, true >,
                         cudaFuncAttributeMaxDynamicSharedMemorySize, SMEM_DYN);
    cudaFuncSetAttribute(moe_gemm_h<false, false, true,  false, false>,
                         cudaFuncAttributeMaxDynamicSharedMemorySize, SMEM_DYN);

    // Launch order (profiler captures our launch index 3):
    //   0 = prep_all, 1 = build_perm, 2 = L1, 3 = L2 <-- ncu, 4 = L3, 5 = L4
    prep_all_kernel<<<TR_BLOCKS + F2H_BLOCKS, 256>>>(
        x, xh, W_de1, W_nl1, W_de2, W_nl2, W_d1, W_d2,
        Wt_e1, Wt_e2, Wt_d1, Wt_d2);
    build_perm_kernel<<<(M + 255) / 256, 256>>>(lang, M);

    // L1: h1 = relu(x[perm] @ W1_e + b1_e)   [split, gather]
    moe_gemm_h<true, true, false, true, true>
        <<<dim3(HID / BN, M / BM, 2), NTHR, SMEM_DYN>>>(
        xh, Wt_e1, Wt_e1 + (size_t)HID * D_IN, b_de1, b_nl1, h1, M, HID, D_IN);

    // L2: enc = h1 @ W2_e + b2_e             [split]
    moe_gemm_h<false, false, false, true, true>
        <<<dim3(INTD / BN, M / BM, 2), NTHR, SMEM_DYN>>>(
        h1, Wt_e2, Wt_e2 + (size_t)INTD * HID, b_de2, b_nl2, enc, M, INTD, HID);

    // L3: h1 = relu(enc @ W_d1 + b_d1)       [shared decoder]
    moe_gemm_h<true, false, false, false, true>
        <<<dim3(HID / BN, M / BM, 1), NTHR, SMEM_DYN>>>(
        enc, Wt_d1, Wt_d1, b_d1, b_d1, h1, M, HID, INTD);

    // L4: out[perm] = h1 @ W_d2 + b_d2       [scatter, f32 out]
    moe_gemm_h<false, false, true, false, false>
        <<<dim3(D_IN / BN, M / BM, 1), NTHR, SMEM_DYN>>>(
        h1, Wt_d2, Wt_d2, b_d2, b_d2, out, M, D_IN, HID);
}

// round 15
// speedup vs baseline: 3.1583x; 1.0014x over previous
#include <cuda_runtime.h>
#include <cuda_fp16.h>
#include <cstdint>
#include <cstddef>

// Problem shapes (fixed)
#define NROWS 32768
#define D_IN  1024
#define HID   1024
#define INTD  2048

// GEMM tiling: 128x128 CTA tile, 2x2 warps of 64x64, K-chunk 64 halfs.
// 2 CTAs/SM; 3-stage cp.async pipeline with ONE barrier per iteration.
#define BM 128
#define BN 128
#define BK 64
#define STAGES 3
#define ROWB 128                            // 64 halfs, no pad (XOR swizzle)
#define A_ST (BM * ROWB)                    // 16384
#define B_ST (BN * ROWB)                    // 16384
#define STAGE_BYTES (A_ST + B_ST)           // 32768
#define SMEM_DYN (STAGES * STAGE_BYTES)     // 98304 (x2 CTAs = 192KB/SM)
#define NTHR 128

// ---------------- scratch (device globals: allocation-free rule) ------------
__device__ int    g_cnt0, g_cnt1;
__device__ int    g_perm[NROWS];
__device__ __half g_xh [(size_t)NROWS * D_IN];
__device__ __half g_h1 [(size_t)NROWS * HID];
__device__ __half g_enc[(size_t)NROWS * INTD];
// Pre-transposed half weights: [n][k] K-major
__device__ __half g_Wt_e1[(size_t)2 * HID  * D_IN];
__device__ __half g_Wt_e2[(size_t)2 * INTD * HID ];
__device__ __half g_Wt_d1[(size_t)HID  * INTD];
__device__ __half g_Wt_d2[(size_t)D_IN * HID ];

// ---------------- helpers ----------------------------------------------------
__device__ __forceinline__ uint32_t smem_u32(const void* p) {
    uint32_t a;
    asm("{ .reg .u64 t; cvta.to.shared.u64 t, %1; cvt.u32.u64 %0, t; }" : "=r"(a) : "l"(p));
    return a;
}

#define CP_ASYNC16(dst, src, sz) \
    asm volatile("cp.async.cg.shared.global [%0], [%1], 16, %2;" \
                 :: "r"(dst), "l"(src), "r"(sz) : "memory")
#define CP_COMMIT() asm volatile("cp.async.commit_group;" ::: "memory")
#define CP_WAIT(n)  asm volatile("cp.async.wait_group %0;" :: "n"(n) : "memory")

#define LDSM_X4(r0, r1, r2, r3, addr) \
    asm volatile("ldmatrix.sync.aligned.m8n8.x4.shared.b16 {%0,%1,%2,%3}, [%4];" \
                 : "=r"(r0), "=r"(r1), "=r"(r2), "=r"(r3) : "r"(addr))

#define MMA16816(d, a, b0, b1) \
    asm volatile("mma.sync.aligned.m16n8k16.row.col.f32.f16.f16.f32 " \
                 "{%0,%1,%2,%3}, {%4,%5,%6,%7}, {%8,%9}, {%0,%1,%2,%3};" \
                 : "+f"((d)[0]), "+f"((d)[1]), "+f"((d)[2]), "+f"((d)[3]) \
                 : "r"((a)[0]), "r"((a)[1]), "r"((a)[2]), "r"((a)[3]), \
                   "r"(b0), "r"(b1))

// ---------------- routing ----------------------------------------------------
__global__ void build_perm_kernel(const int* __restrict__ lang, int n) {
    int i = blockIdx.x * blockDim.x + threadIdx.x;
    if (i < n) {
        if (lang[i] == 0) g_perm[atomicAdd(&g_cnt0, 1)] = i;
        else              g_perm[n - 1 - atomicAdd(&g_cnt1, 1)] = i;
    }
}

// ---------------- prep: ONE kernel for counters + f2h(x) + all transposes ----
#define TR_BLOCKS 9216
#define F2H_BLOCKS 16384            // 32768*1024 / 8 / 256
__global__ void prep_all_kernel(
    const float* __restrict__ x, __half* __restrict__ xh,
    const float* __restrict__ W_de1, const float* __restrict__ W_nl1,
    const float* __restrict__ W_de2, const float* __restrict__ W_nl2,
    const float* __restrict__ W_d1,  const float* __restrict__ W_d2,
    __half* __restrict__ Wt_e1, __half* __restrict__ Wt_e2,
    __half* __restrict__ Wt_d1, __half* __restrict__ Wt_d2)
{
    const int bid = blockIdx.x;
    const int tid = threadIdx.x;
    if (bid == 0 && tid == 0) { g_cnt0 = 0; g_cnt1 = 0; }

    if (bid >= TR_BLOCKS) {
        int i = ((bid - TR_BLOCKS) * 256 + tid) * 8;
        float4 a = *(const float4*)(x + i);
        float4 b = *(const float4*)(x + i + 4);
        __half h[8];
        h[0] = __float2half_rn(a.x); h[1] = __float2half_rn(a.y);
        h[2] = __float2half_rn(a.z); h[3] = __float2half_rn(a.w);
        h[4] = __float2half_rn(b.x); h[5] = __float2half_rn(b.y);
        h[6] = __float2half_rn(b.z); h[7] = __float2half_rn(b.w);
        *(uint4*)(xh + i) = *(const uint4*)h;
        return;
    }

    const float* in; __half* out; int K, N, tile;
    if      (bid < 1024) { in = W_de1; out = Wt_e1;                      K = 1024; N = 1024; tile = bid; }
    else if (bid < 2048) { in = W_nl1; out = Wt_e1 + (size_t)HID * D_IN; K = 1024; N = 1024; tile = bid - 1024; }
    else if (bid < 4096) { in = W_de2; out = Wt_e2;                      K = 1024; N = 2048; tile = bid - 2048; }
    else if (bid < 6144) { in = W_nl2; out = Wt_e2 + (size_t)INTD * HID; K = 1024; N = 2048; tile = bid - 4096; }
    else if (bid < 8192) { in = W_d1;  out = Wt_d1;                      K = 2048; N = 1024; tile = bid - 6144; }
    else                 { in = W_d2;  out = Wt_d2;                      K = 1024; N = 1024; tile = bid - 8192; }

    __shared__ float t[32][33];
    const int tx = tid & 31;
    const int ty = tid >> 5;
    const int ntx = N / 32;
    const int n0 = (tile % ntx) * 32;
    const int k0 = (tile / ntx) * 32;
    #pragma unroll
    for (int j = ty; j < 32; j += 8)
        t[j][tx] = in[(size_t)(k0 + j) * N + n0 + tx];
    __syncthreads();
    #pragma unroll
    for (int j = ty; j < 32; j += 8)
        out[(size_t)(n0 + j) * K + k0 + tx] = __float2half_rn(t[tx][j]);
}

// ---------------- fp16 tensor-core GEMM --------------------------------------
// C[M,N] = act(A @ Bt^T + bias). A: [M,K] half. Bt: [N,K] half (K-major).
// 128x128 CTA tile, 4 warps (2x2 of 64x64). 3-stage pipeline, one barrier:
//   iter i: CP_WAIT(1) [chunk i ready]; bar; issue(i+2); compute(i)
// Stage (i+2)%3 == stage consumed at iter i-1 -> free once the barrier passes.
// Group accounting: outstanding at each wait = {i+1, i+2} -> CP_WAIT(1) blocks
// until group i+1... waits until <=1 pending, i.e. group i+1 done? No: it
// leaves the NEWEST pending; order is FIFO so it retires i+1 first. At iter i
// the outstanding set is {i, i+1}; CP_WAIT(1) retires group i. Exact.
template<bool RELU, bool GATHER, bool SCATTER, bool SPLIT, bool OUT_HALF>
__global__ void __launch_bounds__(NTHR, 2)
moe_gemm_h(const __half* __restrict__ A,
           const __half* __restrict__ Bt0, const __half* __restrict__ Bt1,
           const float* __restrict__ bias0, const float* __restrict__ bias1,
           void* __restrict__ Cv, int M, int N, int K)
{
    const int n0 = SPLIT ? g_cnt0 : M;
    const int e  = SPLIT ? (int)blockIdx.z : 0;
    const int lo = (e == 0) ? 0  : n0;
    const int hi = (e == 0) ? n0 : M;
    const int row0 = blockIdx.y * BM;
    if (SPLIT && (row0 >= hi || row0 + BM <= lo)) return;
    const int col0 = blockIdx.x * BN;

    const __half* __restrict__ Bt   = (e == 0) ? Bt0   : Bt1;
    const float*  __restrict__ bias = (e == 0) ? bias0 : bias1;

    extern __shared__ char smem[];
    const uint32_t sbase = smem_u32(smem);

    const int tid  = threadIdx.x;
    const int warp = tid >> 5;
    const int lane = tid & 31;
    const int warpM = warp >> 1;      // 0..1 (64 rows)
    const int warpN = warp & 1;       // 0..1 (64 cols)
    const int g  = lane >> 2;         // 0..7
    const int tg = lane & 3;          // 0..3

    // ---- fill addressing (granule = 16B = 8 halfs; 8 granules per row) ----
    // A: 128 rows x 8 gr = 1024 slots -> 8/thread. B: same.
    const __half* aSrcp[8];
    uint32_t aDstp[8], aSz[8];
    #pragma unroll
    for (int s = 0; s < 8; s++) {
        int idx = tid + s * NTHR;
        int r = idx >> 3, gr = idx & 7;
        int m = row0 + r;
        bool v = (!SPLIT) || (m >= lo && m < hi);
        aSz[s]   = v ? 16u : 0u;
        aSrcp[s] = A + (size_t)(GATHER ? (v ? g_perm[m] : 0) : m) * K + gr * 8;
        aDstp[s] = sbase + (uint32_t)(r * ROWB + ((gr ^ (r & 7)) * 16));
    }
    const __half* bSrcp[8];
    uint32_t bDstp[8];
    #pragma unroll
    for (int s = 0; s < 8; s++) {
        int idx = tid + s * NTHR;
        int r = idx >> 3, gr = idx & 7;
        bSrcp[s] = Bt + (size_t)(col0 + r) * K + gr * 8;
        bDstp[s] = sbase + A_ST + (uint32_t)(r * ROWB + ((gr ^ (r & 7)) * 16));
    }

    const int nch = K / BK;

    auto issue_all = [&](int c) {
        const uint32_t so = (uint32_t)((c % STAGES) * STAGE_BYTES);
        const int ko = c * BK;
        #pragma unroll
        for (int s = 0; s < 8; s++)
            CP_ASYNC16(aDstp[s] + so, aSrcp[s] + ko, aSz[s]);
        #pragma unroll
        for (int s = 0; s < 8; s++)
            CP_ASYNC16(bDstp[s] + so, bSrcp[s] + ko, 16u);
        CP_COMMIT();
    };

    issue_all(0);
    issue_all(1);

    float acc[4][8][4];
    #pragma unroll
    for (int mt = 0; mt < 4; mt++)
        #pragma unroll
        for (int nt = 0; nt < 8; nt++)
            #pragma unroll
            for (int i = 0; i < 4; i++) acc[mt][nt][i] = 0.0f;

    // per-warp ldmatrix row bases + swizzle masks
    uint32_t aRowOff[4]; int aRm[4];
    #pragma unroll
    for (int mt = 0; mt < 4; mt++) {
        int rr = warpM * 64 + mt * 16 + (lane & 15);
        aRowOff[mt] = sbase + (uint32_t)(rr * ROWB);
        aRm[mt] = rr & 7;
    }
    const int aChunk = lane >> 4;                 // 0..1
    uint32_t bRowOff[4]; int bRm[4];
    #pragma unroll
    for (int p = 0; p < 4; p++) {
        int rr = warpN * 64 + p * 16 + (lane & 7) + ((lane >> 4) << 3);
        bRowOff[p] = sbase + A_ST + (uint32_t)(rr * ROWB);
        bRm[p] = rr & 7;
    }
    const int bChunk = (lane >> 3) & 1;           // 0..1

    uint32_t af[2][4][4], bf[2][4][4];

    auto load_frags = [&](int buf, uint32_t so, int kh) {
        #pragma unroll
        for (int mt = 0; mt < 4; mt++) {
            uint32_t ad = aRowOff[mt] + so
                + (uint32_t)(((kh * 2 + aChunk) ^ aRm[mt]) * 16);
            LDSM_X4(af[buf][mt][0], af[buf][mt][1], af[buf][mt][2], af[buf][mt][3], ad);
        }
        #pragma unroll
        for (int p = 0; p < 4; p++) {
            uint32_t bd = bRowOff[p] + so
                + (uint32_t)(((kh * 2 + bChunk) ^ bRm[p]) * 16);
            LDSM_X4(bf[buf][p][0], bf[buf][p][1], bf[buf][p][2], bf[buf][p][3], bd);
        }
    };

    for (int i = 0; i < nch; i++) {
        CP_WAIT(1);               // outstanding {i, i+1}: retires group i (FIFO)
        __syncthreads();          // all copies of stage i%3 visible to all warps

        // stage (i+2)%3 == (i-1)%3: fully consumed before every warp passed the
        // barrier above -> safe to refill now; overlaps the whole compute below.
        if (i + 2 < nch) issue_all(i + 2);
        else             CP_COMMIT();        // empty group keeps wait math exact

        const uint32_t so = (uint32_t)((i % STAGES) * STAGE_BYTES);
        load_frags(0, so, 0);
        #pragma unroll
        for (int kh = 0; kh < BK / 16; kh++) {    // 4 k-steps of 16
            const int cur = kh & 1;
            if (kh + 1 < BK / 16) load_frags(cur ^ 1, so, kh + 1);
            #pragma unroll
            for (int mt = 0; mt < 4; mt++)
                #pragma unroll
                for (int nt = 0; nt < 8; nt++)
                    MMA16816(acc[mt][nt], af[cur][mt],
                             bf[cur][nt >> 1][(nt & 1) * 2],
                             bf[cur][nt >> 1][(nt & 1) * 2 + 1]);
        }
    }

    // ---- epilogue ----
    #pragma unroll
    for (int mt = 0; mt < 4; mt++) {
        const int mBase = row0 + warpM * 64 + mt * 16 + g;
        #pragma unroll
        for (int nt = 0; nt < 8; nt++) {
            const int c = col0 + warpN * 64 + nt * 8 + 2 * tg;
            const float bv0 = bias[c];
            const float bv1 = bias[c + 1];
            #pragma unroll
            for (int half_i = 0; half_i < 2; half_i++) {
                const int m = mBase + half_i * 8;
                if (SPLIT && (m < lo || m >= hi)) continue;
                float v0 = acc[mt][nt][half_i * 2 + 0] + bv0;
                float v1 = acc[mt][nt][half_i * 2 + 1] + bv1;
                if (RELU) { v0 = fmaxf(v0, 0.f); v1 = fmaxf(v1, 0.f); }
                const int mo = SCATTER ? g_perm[m] : m;
                if (OUT_HALF) {
                    __half2 hv;
                    hv.x = __float2half_rn(v0);
                    hv.y = __float2half_rn(v1);
                    *(__half2*)((__half*)Cv + (size_t)mo * N + c) = hv;
                } else {
                    *(float2*)((float*)Cv + (size_t)mo * N + c) = make_float2(v0, v1);
                }
            }
        }
    }
}

// ---------------- launch ------------------------------------------------------
extern "C" void kernel_launch(void* const* d_in, const int* in_sizes, int n_in,
                              void* d_out, int out_size)
{
    const float* x     = (const float*)d_in[0];
    const int*   lang  = (const int*)  d_in[1];
    const float* W_de1 = (const float*)d_in[2];
    const float* b_de1 = (const float*)d_in[3];
    const float* W_de2 = (const float*)d_in[4];
    const float* b_de2 = (const float*)d_in[5];
    const float* W_nl1 = (const float*)d_in[6];
    const float* b_nl1 = (const float*)d_in[7];
    const float* W_nl2 = (const float*)d_in[8];
    const float* b_nl2 = (const float*)d_in[9];
    const float* W_d1  = (const float*)d_in[10];
    const float* b_d1  = (const float*)d_in[11];
    const float* W_d2  = (const float*)d_in[12];
    const float* b_d2  = (const float*)d_in[13];
    float* out = (float*)d_out;

    const int M = in_sizes[1];  // 32768

    __half *xh, *h1, *enc, *Wt_e1, *Wt_e2, *Wt_d1, *Wt_d2;
    cudaGetSymbolAddress((void**)&xh,    g_xh);
    cudaGetSymbolAddress((void**)&h1,    g_h1);
    cudaGetSymbolAddress((void**)&enc,   g_enc);
    cudaGetSymbolAddress((void**)&Wt_e1, g_Wt_e1);
    cudaGetSymbolAddress((void**)&Wt_e2, g_Wt_e2);
    cudaGetSymbolAddress((void**)&Wt_d1, g_Wt_d1);
    cudaGetSymbolAddress((void**)&Wt_d2, g_Wt_d2);

    cudaFuncSetAttribute(moe_gemm_h<true,  true,  false, true,  true >,
                         cudaFuncAttributeMaxDynamicSharedMemorySize, SMEM_DYN);
    cudaFuncSetAttribute(moe_gemm_h<false, false, false, true,  true >,
                         cudaFuncAttributeMaxDynamicSharedMemorySize, SMEM_DYN);
    cudaFuncSetAttribute(moe_gemm_h<true,  false, false, false, true >,
                         cudaFuncAttributeMaxDynamicSharedMemorySize, SMEM_DYN);
    cudaFuncSetAttribute(moe_gemm_h<false, false, true,  false, false>,
                         cudaFuncAttributeMaxDynamicSharedMemorySize, SMEM_DYN);

    // Launch order (profiler captures our launch index 3):
    //   0 = prep_all, 1 = build_perm, 2 = L1, 3 = L2 <-- ncu, 4 = L3, 5 = L4
    prep_all_kernel<<<TR_BLOCKS + F2H_BLOCKS, 256>>>(
        x, xh, W_de1, W_nl1, W_de2, W_nl2, W_d1, W_d2,
        Wt_e1, Wt_e2, Wt_d1, Wt_d2);
    build_perm_kernel<<<(M + 255) / 256, 256>>>(lang, M);

    // L1: h1 = relu(x[perm] @ W1_e + b1_e)   [split, gather]
    moe_gemm_h<true, true, false, true, true>
        <<<dim3(HID / BN, M / BM, 2), NTHR, SMEM_DYN>>>(
        xh, Wt_e1, Wt_e1 + (size_t)HID * D_IN, b_de1, b_nl1, h1, M, HID, D_IN);

    // L2: enc = h1 @ W2_e + b2_e             [split]
    moe_gemm_h<false, false, false, true, true>
        <<<dim3(INTD / BN, M / BM, 2), NTHR, SMEM_DYN>>>(
        h1, Wt_e2, Wt_e2 + (size_t)INTD * HID, b_de2, b_nl2, enc, M, INTD, HID);

    // L3: h1 = relu(enc @ W_d1 + b_d1)       [shared decoder]
    moe_gemm_h<true, false, false, false, true>
        <<<dim3(HID / BN, M / BM, 1), NTHR, SMEM_DYN>>>(
        enc, Wt_d1, Wt_d1, b_d1, b_d1, h1, M, HID, INTD);

    // L4: out[perm] = h1 @ W_d2 + b_d2       [scatter, f32 out]
    moe_gemm_h<false, false, true, false, false>
        <<<dim3(D_IN / BN, M / BM, 1), NTHR, SMEM_DYN>>>(
        h1, Wt_d2, Wt_d2, b_d2, b_d2, out, M, D_IN, HID);
}

// round 16
// speedup vs baseline: 3.5155x; 1.1131x over previous
#include <cuda_runtime.h>
#include <cuda_fp16.h>
#include <cstdint>
#include <cstddef>

// Problem shapes (fixed)
#define NROWS 32768
#define D_IN  1024
#define HID   1024
#define INTD  2048

// GEMM tiling: 128x128 CTA tile, 2x2 warps of 64x64, K-chunk 64 halfs.
// 2 CTAs/SM; 3-stage cp.async pipeline, one barrier per chunk, cross-chunk
// fragment pipelining (no LDSM drain at chunk boundaries).
#define BM 128
#define BN 128
#define BK 64
#define STAGES 3
#define ROWB 128                            // 64 halfs, no pad (XOR swizzle)
#define A_ST (BM * ROWB)                    // 16384
#define B_ST (BN * ROWB)                    // 16384
#define STAGE_BYTES (A_ST + B_ST)           // 32768
#define SMEM_DYN (STAGES * STAGE_BYTES)     // 98304 (x2 CTAs = 192KB/SM)
#define NTHR 128

// ---------------- scratch (device globals: allocation-free rule) ------------
__device__ int    g_cnt0, g_cnt1;
__device__ int    g_perm[NROWS];
__device__ __half g_xh [(size_t)NROWS * D_IN];
__device__ __half g_h1 [(size_t)NROWS * HID];
__device__ __half g_enc[(size_t)NROWS * INTD];
// Pre-transposed half weights: [n][k] K-major
__device__ __half g_Wt_e1[(size_t)2 * HID  * D_IN];
__device__ __half g_Wt_e2[(size_t)2 * INTD * HID ];
__device__ __half g_Wt_d1[(size_t)HID  * INTD];
__device__ __half g_Wt_d2[(size_t)D_IN * HID ];

// ---------------- helpers ----------------------------------------------------
__device__ __forceinline__ uint32_t smem_u32(const void* p) {
    uint32_t a;
    asm("{ .reg .u64 t; cvta.to.shared.u64 t, %1; cvt.u32.u64 %0, t; }" : "=r"(a) : "l"(p));
    return a;
}

#define CP_ASYNC16(dst, src, sz) \
    asm volatile("cp.async.cg.shared.global [%0], [%1], 16, %2;" \
                 :: "r"(dst), "l"(src), "r"(sz) : "memory")
#define CP_COMMIT() asm volatile("cp.async.commit_group;" ::: "memory")
#define CP_WAIT(n)  asm volatile("cp.async.wait_group %0;" :: "n"(n) : "memory")

#define LDSM_X4(r0, r1, r2, r3, addr) \
    asm volatile("ldmatrix.sync.aligned.m8n8.x4.shared.b16 {%0,%1,%2,%3}, [%4];" \
                 : "=r"(r0), "=r"(r1), "=r"(r2), "=r"(r3) : "r"(addr))

#define MMA16816(d, a, b0, b1) \
    asm volatile("mma.sync.aligned.m16n8k16.row.col.f32.f16.f16.f32 " \
                 "{%0,%1,%2,%3}, {%4,%5,%6,%7}, {%8,%9}, {%0,%1,%2,%3};" \
                 : "+f"((d)[0]), "+f"((d)[1]), "+f"((d)[2]), "+f"((d)[3]) \
                 : "r"((a)[0]), "r"((a)[1]), "r"((a)[2]), "r"((a)[3]), \
                   "r"(b0), "r"(b1))

// ---------------- routing ----------------------------------------------------
__global__ void build_perm_kernel(const int* __restrict__ lang, int n) {
    int i = blockIdx.x * blockDim.x + threadIdx.x;
    if (i < n) {
        if (lang[i] == 0) g_perm[atomicAdd(&g_cnt0, 1)] = i;
        else              g_perm[n - 1 - atomicAdd(&g_cnt1, 1)] = i;
    }
}

// ---------------- prep: ONE kernel for counters + f2h(x) + all transposes ----
#define TR_BLOCKS 9216
#define F2H_BLOCKS 16384            // 32768*1024 / 8 / 256
__global__ void prep_all_kernel(
    const float* __restrict__ x, __half* __restrict__ xh,
    const float* __restrict__ W_de1, const float* __restrict__ W_nl1,
    const float* __restrict__ W_de2, const float* __restrict__ W_nl2,
    const float* __restrict__ W_d1,  const float* __restrict__ W_d2,
    __half* __restrict__ Wt_e1, __half* __restrict__ Wt_e2,
    __half* __restrict__ Wt_d1, __half* __restrict__ Wt_d2)
{
    const int bid = blockIdx.x;
    const int tid = threadIdx.x;
    if (bid == 0 && tid == 0) { g_cnt0 = 0; g_cnt1 = 0; }

    if (bid >= TR_BLOCKS) {
        int i = ((bid - TR_BLOCKS) * 256 + tid) * 8;
        float4 a = *(const float4*)(x + i);
        float4 b = *(const float4*)(x + i + 4);
        __half h[8];
        h[0] = __float2half_rn(a.x); h[1] = __float2half_rn(a.y);
        h[2] = __float2half_rn(a.z); h[3] = __float2half_rn(a.w);
        h[4] = __float2half_rn(b.x); h[5] = __float2half_rn(b.y);
        h[6] = __float2half_rn(b.z); h[7] = __float2half_rn(b.w);
        *(uint4*)(xh + i) = *(const uint4*)h;
        return;
    }

    const float* in; __half* out; int K, N, tile;
    if      (bid < 1024) { in = W_de1; out = Wt_e1;                      K = 1024; N = 1024; tile = bid; }
    else if (bid < 2048) { in = W_nl1; out = Wt_e1 + (size_t)HID * D_IN; K = 1024; N = 1024; tile = bid - 1024; }
    else if (bid < 4096) { in = W_de2; out = Wt_e2;                      K = 1024; N = 2048; tile = bid - 2048; }
    else if (bid < 6144) { in = W_nl2; out = Wt_e2 + (size_t)INTD * HID; K = 1024; N = 2048; tile = bid - 4096; }
    else if (bid < 8192) { in = W_d1;  out = Wt_d1;                      K = 2048; N = 1024; tile = bid - 6144; }
    else                 { in = W_d2;  out = Wt_d2;                      K = 1024; N = 1024; tile = bid - 8192; }

    __shared__ float t[32][33];
    const int tx = tid & 31;
    const int ty = tid >> 5;
    const int ntx = N / 32;
    const int n0 = (tile % ntx) * 32;
    const int k0 = (tile / ntx) * 32;
    #pragma unroll
    for (int j = ty; j < 32; j += 8)
        t[j][tx] = in[(size_t)(k0 + j) * N + n0 + tx];
    __syncthreads();
    #pragma unroll
    for (int j = ty; j < 32; j += 8)
        out[(size_t)(n0 + j) * K + k0 + tx] = __float2half_rn(t[tx][j]);
}

// ---------------- fp16 tensor-core GEMM --------------------------------------
// C[M,N] = act(A @ Bt^T + bias). A: [M,K] half. Bt: [N,K] half (K-major).
// 128x128 CTA tile, 4 warps (2x2 of 64x64), 3-stage pipeline.
//   prologue: issue(0), issue(1); wait stage0; preload frags(chunk0, kh0)
//   iter i:   CP_WAIT(0)  [all groups <= i+1 done -> stages i, i+1 ready]
//             bar; issue(i+2) into stage (i-1)%3 (freed at iter i-1)
//             kh=0..2: prefetch frags kh+1 (same stage); MMA kh
//             kh=3:    prefetch frags chunk i+1 kh0 from stage (i+1)%3; MMA
// Fragment stream never drains at chunk boundaries; one barrier per chunk.
template<bool RELU, bool GATHER, bool SCATTER, bool SPLIT, bool OUT_HALF>
__global__ void __launch_bounds__(NTHR, 2)
moe_gemm_h(const __half* __restrict__ A,
           const __half* __restrict__ Bt0, const __half* __restrict__ Bt1,
           const float* __restrict__ bias0, const float* __restrict__ bias1,
           void* __restrict__ Cv, int M, int N, int K)
{
    const int n0 = SPLIT ? g_cnt0 : M;
    const int e  = SPLIT ? (int)blockIdx.z : 0;
    const int lo = (e == 0) ? 0  : n0;
    const int hi = (e == 0) ? n0 : M;
    const int row0 = blockIdx.y * BM;
    if (SPLIT && (row0 >= hi || row0 + BM <= lo)) return;
    const int col0 = blockIdx.x * BN;

    const __half* __restrict__ Bt   = (e == 0) ? Bt0   : Bt1;
    const float*  __restrict__ bias = (e == 0) ? bias0 : bias1;

    extern __shared__ char smem[];
    const uint32_t sbase = smem_u32(smem);

    const int tid  = threadIdx.x;
    const int warp = tid >> 5;
    const int lane = tid & 31;
    const int warpM = warp >> 1;      // 0..1 (64 rows)
    const int warpN = warp & 1;       // 0..1 (64 cols)
    const int g  = lane >> 2;         // 0..7
    const int tg = lane & 3;          // 0..3

    // ---- fill addressing: minimal register state, strided slots -------------
    // slot s covers row r0 + 16*s, granule gr0. (r&7) invariant under +16s, so
    // dst offsets stride by 16*ROWB = 2048 with a fixed swizzle.
    const int r0  = tid >> 3;         // 0..15
    const int gr0 = tid & 7;          // 0..7
    const uint32_t dstSwz = (uint32_t)(r0 * ROWB + ((gr0 ^ (r0 & 7)) * 16));
    const uint32_t aDst0 = sbase + dstSwz;
    const uint32_t bDst0 = sbase + A_ST + dstSwz;
    const size_t rowStride = (size_t)16 * K;   // halfs between slots

    const __half* aSrcArr[8];                  // only materialized when GATHER
    if (GATHER) {
        #pragma unroll
        for (int s = 0; s < 8; s++) {
            int m = row0 + r0 + 16 * s;
            bool v = (!SPLIT) || (m >= lo && m < hi);
            aSrcArr[s] = A + (size_t)(v ? g_perm[m] : 0) * K + gr0 * 8;
        }
    }
    const __half* aSrc0 = A  + (size_t)(row0 + r0) * K + gr0 * 8;
    const __half* bSrc0 = Bt + (size_t)(col0 + r0) * K + gr0 * 8;

    const int nch = K / BK;

    auto issue_all = [&](int c) {
        const uint32_t so = (uint32_t)((c % STAGES) * STAGE_BYTES);
        const int ko = c * BK;
        #pragma unroll
        for (int s = 0; s < 8; s++) {
            uint32_t sz = 16u;
            if (SPLIT) {
                int m = row0 + r0 + 16 * s;
                sz = (m >= lo && m < hi) ? 16u : 0u;
            }
            const __half* src = GATHER ? (aSrcArr[s] + ko)
                                       : (aSrc0 + ko + s * rowStride);
            CP_ASYNC16(aDst0 + so + s * 2048u, src, sz);
        }
        #pragma unroll
        for (int s = 0; s < 8; s++)
            CP_ASYNC16(bDst0 + so + s * 2048u, bSrc0 + ko + s * rowStride, 16u);
        CP_COMMIT();
    };

    float acc[4][8][4];
    #pragma unroll
    for (int mt = 0; mt < 4; mt++)
        #pragma unroll
        for (int nt = 0; nt < 8; nt++)
            #pragma unroll
            for (int i = 0; i < 4; i++) acc[mt][nt][i] = 0.0f;

    // per-warp ldmatrix row bases + swizzle masks
    uint32_t aRowOff[4]; int aRm[4];
    #pragma unroll
    for (int mt = 0; mt < 4; mt++) {
        int rr = warpM * 64 + mt * 16 + (lane & 15);
        aRowOff[mt] = sbase + (uint32_t)(rr * ROWB);
        aRm[mt] = rr & 7;
    }
    const int aChunk = lane >> 4;                 // 0..1
    uint32_t bRowOff[4]; int bRm[4];
    #pragma unroll
    for (int p = 0; p < 4; p++) {
        int rr = warpN * 64 + p * 16 + (lane & 7) + ((lane >> 4) << 3);
        bRowOff[p] = sbase + A_ST + (uint32_t)(rr * ROWB);
        bRm[p] = rr & 7;
    }
    const int bChunk = (lane >> 3) & 1;           // 0..1

    uint32_t af[2][4][4], bf[2][4][4];

    auto load_frags = [&](int buf, uint32_t so, int kh) {
        #pragma unroll
        for (int mt = 0; mt < 4; mt++) {
            uint32_t ad = aRowOff[mt] + so
                + (uint32_t)(((kh * 2 + aChunk) ^ aRm[mt]) * 16);
            LDSM_X4(af[buf][mt][0], af[buf][mt][1], af[buf][mt][2], af[buf][mt][3], ad);
        }
        #pragma unroll
        for (int p = 0; p < 4; p++) {
            uint32_t bd = bRowOff[p] + so
                + (uint32_t)(((kh * 2 + bChunk) ^ bRm[p]) * 16);
            LDSM_X4(bf[buf][p][0], bf[buf][p][1], bf[buf][p][2], bf[buf][p][3], bd);
        }
    };

    // ---- prologue ----
    issue_all(0);
    issue_all(1);
    CP_WAIT(1);                  // stage 0 complete
    __syncthreads();
    load_frags(0, 0u, 0);        // chunk 0, kh 0 -> buf 0

    for (int i = 0; i < nch; i++) {
        CP_WAIT(0);              // all groups <= i+1 done: stages i, i+1 ready
        __syncthreads();
        if (i + 2 < nch) issue_all(i + 2);   // into stage (i-1)%3, freed above

        const uint32_t so  = (uint32_t)((i % STAGES) * STAGE_BYTES);
        const uint32_t son = (uint32_t)(((i + 1) % STAGES) * STAGE_BYTES);
        #pragma unroll
        for (int kh = 0; kh < 4; kh++) {
            const int cur = kh & 1;
            if (kh < 3)             load_frags(cur ^ 1, so,  kh + 1);
            else if (i + 1 < nch)   load_frags(cur ^ 1, son, 0);   // cross-chunk
            #pragma unroll
            for (int mt = 0; mt < 4; mt++)
                #pragma unroll
                for (int nt = 0; nt < 8; nt++)
                    MMA16816(acc[mt][nt], af[cur][mt],
                             bf[cur][nt >> 1][(nt & 1) * 2],
                             bf[cur][nt >> 1][(nt & 1) * 2 + 1]);
        }
    }

    // ---- epilogue ----
    #pragma unroll
    for (int mt = 0; mt < 4; mt++) {
        const int mBase = row0 + warpM * 64 + mt * 16 + g;
        #pragma unroll
        for (int nt = 0; nt < 8; nt++) {
            const int c = col0 + warpN * 64 + nt * 8 + 2 * tg;
            const float bv0 = bias[c];
            const float bv1 = bias[c + 1];
            #pragma unroll
            for (int half_i = 0; half_i < 2; half_i++) {
                const int m = mBase + half_i * 8;
                if (SPLIT && (m < lo || m >= hi)) continue;
                float v0 = acc[mt][nt][half_i * 2 + 0] + bv0;
                float v1 = acc[mt][nt][half_i * 2 + 1] + bv1;
                if (RELU) { v0 = fmaxf(v0, 0.f); v1 = fmaxf(v1, 0.f); }
                const int mo = SCATTER ? g_perm[m] : m;
                if (OUT_HALF) {
                    __half2 hv;
                    hv.x = __float2half_rn(v0);
                    hv.y = __float2half_rn(v1);
                    *(__half2*)((__half*)Cv + (size_t)mo * N + c) = hv;
                } else {
                    *(float2*)((float*)Cv + (size_t)mo * N + c) = make_float2(v0, v1);
                }
            }
        }
    }
}

// ---------------- launch ------------------------------------------------------
extern "C" void kernel_launch(void* const* d_in, const int* in_sizes, int n_in,
                              void* d_out, int out_size)
{
    const float* x     = (const float*)d_in[0];
    const int*   lang  = (const int*)  d_in[1];
    const float* W_de1 = (const float*)d_in[2];
    const float* b_de1 = (const float*)d_in[3];
    const float* W_de2 = (const float*)d_in[4];
    const float* b_de2 = (const float*)d_in[5];
    const float* W_nl1 = (const float*)d_in[6];
    const float* b_nl1 = (const float*)d_in[7];
    const float* W_nl2 = (const float*)d_in[8];
    const float* b_nl2 = (const float*)d_in[9];
    const float* W_d1  = (const float*)d_in[10];
    const float* b_d1  = (const float*)d_in[11];
    const float* W_d2  = (const float*)d_in[12];
    const float* b_d2  = (const float*)d_in[13];
    float* out = (float*)d_out;

    const int M = in_sizes[1];  // 32768

    __half *xh, *h1, *enc, *Wt_e1, *Wt_e2, *Wt_d1, *Wt_d2;
    cudaGetSymbolAddress((void**)&xh,    g_xh);
    cudaGetSymbolAddress((void**)&h1,    g_h1);
    cudaGetSymbolAddress((void**)&enc,   g_enc);
    cudaGetSymbolAddress((void**)&Wt_e1, g_Wt_e1);
    cudaGetSymbolAddress((void**)&Wt_e2, g_Wt_e2);
    cudaGetSymbolAddress((void**)&Wt_d1, g_Wt_d1);
    cudaGetSymbolAddress((void**)&Wt_d2, g_Wt_d2);

    cudaFuncSetAttribute(moe_gemm_h<true,  true,  false, true,  true >,
                         cudaFuncAttributeMaxDynamicSharedMemorySize, SMEM_DYN);
    cudaFuncSetAttribute(moe_gemm_h<false, false, false, true,  true >,
                         cudaFuncAttributeMaxDynamicSharedMemorySize, SMEM_DYN);
    cudaFuncSetAttribute(moe_gemm_h<true,  false, false, false, true >,
                         cudaFuncAttributeMaxDynamicSharedMemorySize, SMEM_DYN);
    cudaFuncSetAttribute(moe_gemm_h<false, false, true,  false, false>,
                         cudaFuncAttributeMaxDynamicSharedMemorySize, SMEM_DYN);

    // Launch order (profiler captures our launch index 3):
    //   0 = prep_all, 1 = build_perm, 2 = L1, 3 = L2 <-- ncu, 4 = L3, 5 = L4
    prep_all_kernel<<<TR_BLOCKS + F2H_BLOCKS, 256>>>(
        x, xh, W_de1, W_nl1, W_de2, W_nl2, W_d1, W_d2,
        Wt_e1, Wt_e2, Wt_d1, Wt_d2);
    build_perm_kernel<<<(M + 255) / 256, 256>>>(lang, M);

    // L1: h1 = relu(x[perm] @ W1_e + b1_e)   [split, gather]
    moe_gemm_h<true, true, false, true, true>
        <<<dim3(HID / BN, M / BM, 2), NTHR, SMEM_DYN>>>(
        xh, Wt_e1, Wt_e1 + (size_t)HID * D_IN, b_de1, b_nl1, h1, M, HID, D_IN);

    // L2: enc = h1 @ W2_e + b2_e             [split]
    moe_gemm_h<false, false, false, true, true>
        <<<dim3(INTD / BN, M / BM, 2), NTHR, SMEM_DYN>>>(
        h1, Wt_e2, Wt_e2 + (size_t)INTD * HID, b_de2, b_nl2, enc, M, INTD, HID);

    // L3: h1 = relu(enc @ W_d1 + b_d1)       [shared decoder]
    moe_gemm_h<true, false, false, false, true>
        <<<dim3(HID / BN, M / BM, 1), NTHR, SMEM_DYN>>>(
        enc, Wt_d1, Wt_d1, b_d1, b_d1, h1, M, HID, INTD);

    // L4: out[perm] = h1 @ W_d2 + b_d2       [scatter, f32 out]
    moe_gemm_h<false, false, true, false, false>
        <<<dim3(D_IN / BN, M / BM, 1), NTHR, SMEM_DYN>>>(
        h1, Wt_d2, Wt_d2, b_d2, b_d2, out, M, D_IN, HID);
}